// round 2
// baseline (speedup 1.0000x reference)
#include <cuda_runtime.h>
#include <math.h>

typedef unsigned long long ull;

#define BT    65536
#define T_LEN 16384
#define RCH   128
#define TM    64
#define KC    32

// Scratch (no cudaMalloc allowed): ~100 MB of __device__ globals.
__device__ float g_resA[BT * RCH];
__device__ float g_resB[BT * RCH];
__device__ float g_outacc[BT * RCH];

// ---------------- packed f32x2 helpers -------------------------------------
__device__ __forceinline__ ull pk2(float lo, float hi) {
    ull r; asm("mov.b64 %0, {%1, %2};" : "=l"(r) : "f"(lo), "f"(hi)); return r;
}
__device__ __forceinline__ void upk2(ull v, float& lo, float& hi) {
    asm("mov.b64 {%0, %1}, %2;" : "=f"(lo), "=f"(hi) : "l"(v));
}
__device__ __forceinline__ void fma2(ull& d, ull a, ull b) {
    asm("fma.rn.f32x2 %0, %1, %2, %0;" : "+l"(d) : "l"(a), "l"(b));
}

// ---------------------------------------------------------------------------
// Initial causal conv: K=32, 64 -> 128, dilation 1.
__global__ void __launch_bounds__(256, 2) init_kernel(
    const float* __restrict__ X, const float* __restrict__ W,
    const float* __restrict__ B, float* __restrict__ res_out)
{
    extern __shared__ float sm[];
    float* xt = sm;            // 96*64 floats (95 rows used)
    float* wb = sm + 96 * 64;  // 64*128 floats
    const int tid  = threadIdx.x;
    const int row0 = blockIdx.x * TM;
    const int batchStart = (row0 / T_LEN) * T_LEN;

    for (int i = tid; i < 95 * 16; i += 256) {
        int r = i >> 4, c4 = i & 15;
        int src = row0 - 31 + r;
        float4 v = make_float4(0.f, 0.f, 0.f, 0.f);
        if (src >= batchStart) v = ((const float4*)(X + (size_t)src * 64))[c4];
        ((float4*)(xt + r * 64))[c4] = v;
    }

    const int ty = tid >> 4, tx = tid & 15;
    const int r0 = ty * 4, c0 = tx * 8;

    ull acc[4][4];
    #pragma unroll
    for (int j = 0; j < 4; j++) {
        ull b = pk2(B[c0 + 2*j], B[c0 + 2*j + 1]);
        #pragma unroll
        for (int rr = 0; rr < 4; rr++) acc[rr][j] = b;
    }

    for (int j = 0; j < 32; j++) {
        __syncthreads();
        const float4* ws = (const float4*)(W + (size_t)j * 64 * 128);
        for (int i = tid; i < 2048; i += 256) ((float4*)wb)[i] = ws[i];
        __syncthreads();
        #pragma unroll 8
        for (int k = 0; k < 64; k++) {
            ulonglong2 wa = *(const ulonglong2*)(wb + k * 128 + c0);
            ulonglong2 wc = *(const ulonglong2*)(wb + k * 128 + c0 + 4);
            #pragma unroll
            for (int rr = 0; rr < 4; rr++) {
                float a = xt[(r0 + rr + j) * 64 + k];
                ull ad = pk2(a, a);
                fma2(acc[rr][0], ad, wa.x);
                fma2(acc[rr][1], ad, wa.y);
                fma2(acc[rr][2], ad, wc.x);
                fma2(acc[rr][3], ad, wc.y);
            }
        }
    }
    #pragma unroll
    for (int rr = 0; rr < 4; rr++) {
        float o[8];
        #pragma unroll
        for (int j = 0; j < 4; j++) upk2(acc[rr][j], o[2*j], o[2*j+1]);
        float* dst = res_out + (size_t)(row0 + r0 + rr) * RCH + c0;
        ((float4*)dst)[0] = make_float4(o[0], o[1], o[2], o[3]);
        ((float4*)dst)[1] = make_float4(o[4], o[5], o[6], o[7]);
    }
}

// ---------------------------------------------------------------------------
__device__ __forceinline__ void bias_init(ull acc[4][4], const float* __restrict__ b, int c0) {
    #pragma unroll
    for (int j = 0; j < 4; j++) {
        ull v = pk2(__ldg(b + c0 + 2*j), __ldg(b + c0 + 2*j + 1));
        #pragma unroll
        for (int rr = 0; rr < 4; rr++) acc[rr][j] = v;
    }
}

// acc += A0 @ W0 + A1 @ W1  (A row-major [TM x 128] smem; W staged [128 x 128])
__device__ __forceinline__ void gemm2p(
    const float* __restrict__ sA0, const float* __restrict__ sA1,
    const float* __restrict__ gW0, const float* __restrict__ gW1,
    float* __restrict__ swb, int r0, int c0, int tid, ull acc[4][4])
{
    for (int kc = 0; kc < RCH; kc += KC) {
        __syncthreads();
        const float4* w0s = (const float4*)(gW0 + kc * RCH);
        const float4* w1s = (const float4*)(gW1 + kc * RCH);
        for (int i = tid; i < (KC * RCH) / 4; i += 256) {
            ((float4*)swb)[i]              = w0s[i];
            ((float4*)(swb + KC*RCH))[i]   = w1s[i];
        }
        __syncthreads();
        #pragma unroll 8
        for (int kk = 0; kk < KC; kk++) {
            int k = kc + kk;
            ulonglong2 wa = *(const ulonglong2*)(swb + kk*RCH + c0);
            ulonglong2 wc = *(const ulonglong2*)(swb + kk*RCH + c0 + 4);
            ulonglong2 va = *(const ulonglong2*)(swb + KC*RCH + kk*RCH + c0);
            ulonglong2 vc = *(const ulonglong2*)(swb + KC*RCH + kk*RCH + c0 + 4);
            #pragma unroll
            for (int rr = 0; rr < 4; rr++) {
                float a0 = sA0[(r0 + rr) * RCH + k];
                float a1 = sA1[(r0 + rr) * RCH + k];
                ull a0d = pk2(a0, a0);
                ull a1d = pk2(a1, a1);
                fma2(acc[rr][0], a0d, wa.x);
                fma2(acc[rr][1], a0d, wa.y);
                fma2(acc[rr][2], a0d, wc.x);
                fma2(acc[rr][3], a0d, wc.y);
                fma2(acc[rr][0], a1d, va.x);
                fma2(acc[rr][1], a1d, va.y);
                fma2(acc[rr][2], a1d, vc.x);
                fma2(acc[rr][3], a1d, vc.y);
            }
        }
    }
}

// accS += A @ Ws ; accR += A @ Wr (same A)
__device__ __forceinline__ void gemmSRp(
    const float* __restrict__ sA,
    const float* __restrict__ gWs, const float* __restrict__ gWr,
    float* __restrict__ swb, int r0, int c0, int tid,
    ull accS[4][4], ull accR[4][4])
{
    for (int kc = 0; kc < RCH; kc += KC) {
        __syncthreads();
        const float4* wss = (const float4*)(gWs + kc * RCH);
        const float4* wrs = (const float4*)(gWr + kc * RCH);
        for (int i = tid; i < (KC * RCH) / 4; i += 256) {
            ((float4*)swb)[i]            = wss[i];
            ((float4*)(swb + KC*RCH))[i] = wrs[i];
        }
        __syncthreads();
        #pragma unroll 8
        for (int kk = 0; kk < KC; kk++) {
            int k = kc + kk;
            ulonglong2 sa = *(const ulonglong2*)(swb + kk*RCH + c0);
            ulonglong2 sc = *(const ulonglong2*)(swb + kk*RCH + c0 + 4);
            ulonglong2 qa = *(const ulonglong2*)(swb + KC*RCH + kk*RCH + c0);
            ulonglong2 qc = *(const ulonglong2*)(swb + KC*RCH + kk*RCH + c0 + 4);
            #pragma unroll
            for (int rr = 0; rr < 4; rr++) {
                float p = sA[(r0 + rr) * RCH + k];
                ull pd = pk2(p, p);
                fma2(accS[rr][0], pd, sa.x);
                fma2(accS[rr][1], pd, sa.y);
                fma2(accS[rr][2], pd, sc.x);
                fma2(accS[rr][3], pd, sc.y);
                fma2(accR[rr][0], pd, qa.x);
                fma2(accR[rr][1], pd, qa.y);
                fma2(accR[rr][2], pd, qc.x);
                fma2(accR[rr][3], pd, qc.y);
            }
        }
    }
}

// ---------------------------------------------------------------------------
// One WaveNet layer, fused.
__global__ void __launch_bounds__(256, 2) layer_kernel(
    const float* __restrict__ res_in, float* __restrict__ res_out,
    float* __restrict__ out_acc,
    const float* __restrict__ fw, const float* __restrict__ fb,
    const float* __restrict__ gw, const float* __restrict__ gb,
    const float* __restrict__ sw, const float* __restrict__ sb,
    const float* __restrict__ rw, const float* __restrict__ rb,
    int d, int first)
{
    extern __shared__ float sm[];
    float* scur  = sm;                 // TM*128  (kept for residual add)
    float* sprev = sm + TM * RCH;      // TM*128  (reused for p)
    float* swb   = sm + 2 * TM * RCH;  // 2*KC*128

    const int tid  = threadIdx.x;
    const int row0 = blockIdx.x * TM;
    const int batchStart = (row0 / T_LEN) * T_LEN;

    {
        const float4* cin = (const float4*)(res_in + (size_t)row0 * RCH);
        for (int i = tid; i < (TM * RCH) / 4; i += 256) ((float4*)scur)[i] = cin[i];
    }
    for (int i = tid; i < (TM * RCH) / 4; i += 256) {
        int r = i >> 5;
        int src = row0 + r - d;
        float4 v = make_float4(0.f, 0.f, 0.f, 0.f);
        if (src >= batchStart) v = ((const float4*)(res_in + (size_t)src * RCH))[i & 31];
        ((float4*)sprev)[i] = v;
    }

    const int ty = tid >> 4, tx = tid & 15;
    const int r0 = ty * 4, c0 = tx * 8;

    ull acc[4][4];

    // f = tanh(prev @ fw0 + cur @ fw1 + fb)  -> registers
    bias_init(acc, fb, c0);
    gemm2p(sprev, scur, fw, fw + RCH*RCH, swb, r0, c0, tid, acc);
    float fv[4][8];
    #pragma unroll
    for (int rr = 0; rr < 4; rr++)
        #pragma unroll
        for (int j = 0; j < 4; j++) {
            float lo, hi; upk2(acc[rr][j], lo, hi);
            fv[rr][2*j]   = tanhf(lo);
            fv[rr][2*j+1] = tanhf(hi);
        }

    // g = sigmoid(...); p = f*g  -> registers
    bias_init(acc, gb, c0);
    gemm2p(sprev, scur, gw, gw + RCH*RCH, swb, r0, c0, tid, acc);
    float pv[4][8];
    #pragma unroll
    for (int rr = 0; rr < 4; rr++)
        #pragma unroll
        for (int j = 0; j < 4; j++) {
            float lo, hi; upk2(acc[rr][j], lo, hi);
            pv[rr][2*j]   = fv[rr][2*j]   / (1.0f + __expf(-lo));
            pv[rr][2*j+1] = fv[rr][2*j+1] / (1.0f + __expf(-hi));
        }
    __syncthreads();   // everyone done reading sprev -> safe to overwrite with p
    #pragma unroll
    for (int rr = 0; rr < 4; rr++) {
        float* dst = sprev + (r0 + rr) * RCH + c0;
        ((float4*)dst)[0] = make_float4(pv[rr][0], pv[rr][1], pv[rr][2], pv[rr][3]);
        ((float4*)dst)[1] = make_float4(pv[rr][4], pv[rr][5], pv[rr][6], pv[rr][7]);
    }

    // skip & residual 1x1 convs
    ull accS[4][4], accR[4][4];
    bias_init(accS, sb, c0);
    bias_init(accR, rb, c0);
    gemmSRp(sprev, sw, rw, swb, r0, c0, tid, accS, accR);

    #pragma unroll
    for (int rr = 0; rr < 4; rr++) {
        float s8[8], q8[8];
        #pragma unroll
        for (int j = 0; j < 4; j++) {
            upk2(accS[rr][j], s8[2*j], s8[2*j+1]);
            upk2(accR[rr][j], q8[2*j], q8[2*j+1]);
        }
        size_t base = (size_t)(row0 + r0 + rr) * RCH + c0;
        if (first) {
            ((float4*)(out_acc + base))[0] = make_float4(s8[0], s8[1], s8[2], s8[3]);
            ((float4*)(out_acc + base))[1] = make_float4(s8[4], s8[5], s8[6], s8[7]);
        } else {
            float4 o0 = ((float4*)(out_acc + base))[0];
            float4 o1 = ((float4*)(out_acc + base))[1];
            o0.x += s8[0]; o0.y += s8[1]; o0.z += s8[2]; o0.w += s8[3];
            o1.x += s8[4]; o1.y += s8[5]; o1.z += s8[6]; o1.w += s8[7];
            ((float4*)(out_acc + base))[0] = o0;
            ((float4*)(out_acc + base))[1] = o1;
        }
        const float* c = scur + (r0 + rr) * RCH + c0;
        ((float4*)(res_out + base))[0] = make_float4(c[0]+q8[0], c[1]+q8[1], c[2]+q8[2], c[3]+q8[3]);
        ((float4*)(res_out + base))[1] = make_float4(c[4]+q8[4], c[5]+q8[5], c[6]+q8[6], c[7]+q8[7]);
    }
}

// ---------------------------------------------------------------------------
// Post chain, fully fused; one warp per row (SC = 32 = warp width).
__global__ void __launch_bounds__(256) post_kernel(
    const float* __restrict__ out_acc,
    const float* __restrict__ s0w, const float* __restrict__ s0b,
    const float* __restrict__ srw, const float* __restrict__ srb,
    const float* __restrict__ fnw, const float* __restrict__ fnb,
    float* __restrict__ y)
{
    extern __shared__ float sm[];
    float* w0 = sm;            // 128*32
    float* wr = w0 + 4096;     // 31*32*32
    float* wf = wr + 31744;    // 32*256
    float* b0 = wf + 8192;     // 32
    float* br = b0 + 32;       // 31*32
    float* bf = br + 992;      // 256

    const int tid = threadIdx.x;
    for (int i = tid; i < 4096;  i += blockDim.x) w0[i] = s0w[i];
    for (int i = tid; i < 31744; i += blockDim.x) wr[i] = srw[i];
    for (int i = tid; i < 8192;  i += blockDim.x) wf[i] = fnw[i];
    for (int i = tid; i < 32;    i += blockDim.x) b0[i] = s0b[i];
    for (int i = tid; i < 992;   i += blockDim.x) br[i] = srb[i];
    for (int i = tid; i < 256;   i += blockDim.x) bf[i] = fnb[i];
    __syncthreads();

    const int warp = tid >> 5, lane = tid & 31;
    const int nwarp = blockDim.x >> 5;

    for (int row = blockIdx.x * nwarp + warp; row < BT; row += gridDim.x * nwarp) {
        float4 x = ((const float4*)(out_acc + (size_t)row * RCH))[lane];
        x.x = fmaxf(x.x, 0.f); x.y = fmaxf(x.y, 0.f);
        x.z = fmaxf(x.z, 0.f); x.w = fmaxf(x.w, 0.f);
        float h = b0[lane];
        #pragma unroll
        for (int s = 0; s < 32; s++) {
            float vx = __shfl_sync(0xffffffffu, x.x, s);
            float vy = __shfl_sync(0xffffffffu, x.y, s);
            float vz = __shfl_sync(0xffffffffu, x.z, s);
            float vw = __shfl_sync(0xffffffffu, x.w, s);
            h += vx * w0[(s*4+0)*32 + lane];
            h += vy * w0[(s*4+1)*32 + lane];
            h += vz * w0[(s*4+2)*32 + lane];
            h += vw * w0[(s*4+3)*32 + lane];
        }
        for (int li = 0; li < 31; li++) {
            float rv = fmaxf(h, 0.f);
            const float* wp = wr + li * 1024;
            float ha = br[li*32 + lane], hb = 0.f;
            #pragma unroll
            for (int s = 0; s < 32; s += 2) {
                float ra  = __shfl_sync(0xffffffffu, rv, s);
                float rb2 = __shfl_sync(0xffffffffu, rv, s + 1);
                ha += ra  * wp[(s    )*32 + lane];
                hb += rb2 * wp[(s + 1)*32 + lane];
            }
            h = ha + hb;
        }
        float rv = fmaxf(h, 0.f);
        float acc[8];
        #pragma unroll
        for (int u = 0; u < 8; u++) acc[u] = bf[lane*8 + u];
        #pragma unroll
        for (int s = 0; s < 32; s++) {
            float rs = __shfl_sync(0xffffffffu, rv, s);
            const float* wp = wf + s*256 + lane*8;
            #pragma unroll
            for (int u = 0; u < 8; u++) acc[u] += rs * wp[u];
        }
        float4* yo = (float4*)(y + (size_t)row * 256 + lane * 8);
        yo[0] = make_float4(acc[0], acc[1], acc[2], acc[3]);
        yo[1] = make_float4(acc[4], acc[5], acc[6], acc[7]);
    }
}

// ---------------------------------------------------------------------------
extern "C" void kernel_launch(void* const* d_in, const int* in_sizes, int n_in,
                              void* d_out, int out_size)
{
    const float* X       = (const float*)d_in[0];
    const float* init_w  = (const float*)d_in[1];
    const float* init_b  = (const float*)d_in[2];
    const float* f_w     = (const float*)d_in[3];
    const float* f_b     = (const float*)d_in[4];
    const float* g_w     = (const float*)d_in[5];
    const float* g_b     = (const float*)d_in[6];
    const float* skip_w  = (const float*)d_in[7];
    const float* skip_b  = (const float*)d_in[8];
    const float* res_w   = (const float*)d_in[9];
    const float* res_b   = (const float*)d_in[10];
    const float* skip0_w = (const float*)d_in[11];
    const float* skip0_b = (const float*)d_in[12];
    const float* skipr_w = (const float*)d_in[13];
    const float* skipr_b = (const float*)d_in[14];
    const float* final_w = (const float*)d_in[15];
    const float* final_b = (const float*)d_in[16];
    float* y = (float*)d_out;

    float *resA, *resB, *outacc;
    cudaGetSymbolAddress((void**)&resA,   g_resA);
    cudaGetSymbolAddress((void**)&resB,   g_resB);
    cudaGetSymbolAddress((void**)&outacc, g_outacc);

    const int INIT_SMEM  = (96*64 + 64*128) * 4;                        // 57344 B
    const int LAYER_SMEM = (2*TM*RCH + 2*KC*RCH) * 4;                   // 98304 B
    const int POST_SMEM  = (4096 + 31744 + 8192 + 32 + 992 + 256) * 4;  // 181248 B
    cudaFuncSetAttribute(init_kernel,  cudaFuncAttributeMaxDynamicSharedMemorySize, INIT_SMEM);
    cudaFuncSetAttribute(layer_kernel, cudaFuncAttributeMaxDynamicSharedMemorySize, LAYER_SMEM);
    cudaFuncSetAttribute(post_kernel,  cudaFuncAttributeMaxDynamicSharedMemorySize, POST_SMEM);

    init_kernel<<<BT / TM, 256, INIT_SMEM>>>(X, init_w, init_b, resA);

    static const int DIL[20] = {1,2,4,8,16,32,64,128,256,512,
                                1,2,4,8,16,32,64,128,256,512};
    for (int i = 0; i < 20; i++) {
        const float* rin  = (i & 1) ? resB : resA;
        float*       rout = (i & 1) ? resA : resB;
        layer_kernel<<<BT / TM, 256, LAYER_SMEM>>>(
            rin, rout, outacc,
            f_w + (size_t)i * 2 * RCH * RCH, f_b + i * RCH,
            g_w + (size_t)i * 2 * RCH * RCH, g_b + i * RCH,
            skip_w + (size_t)i * RCH * RCH,  skip_b + i * RCH,
            res_w + (size_t)i * RCH * RCH,   res_b + i * RCH,
            DIL[i], (i == 0) ? 1 : 0);
    }

    post_kernel<<<592, 256, POST_SMEM>>>(outacc, skip0_w, skip0_b,
                                         skipr_w, skipr_b, final_w, final_b, y);
}

// round 4
// speedup vs baseline: 1.3495x; 1.3495x over previous
#include <cuda_runtime.h>
#include <math.h>

typedef unsigned long long ull;

#define BT    65536
#define T_LEN 16384
#define RCH   128
#define TM    64
#define NT    128
#define KC    32

// Scratch (no cudaMalloc allowed): ~100 MB of __device__ globals.
__device__ float g_resA[BT * RCH];
__device__ float g_resB[BT * RCH];
__device__ float g_outacc[BT * RCH];

// ---------------- packed f32x2 helpers -------------------------------------
__device__ __forceinline__ ull pk2(float lo, float hi) {
    ull r; asm("mov.b64 %0, {%1, %2};" : "=l"(r) : "f"(lo), "f"(hi)); return r;
}
__device__ __forceinline__ void upk2(ull v, float& lo, float& hi) {
    asm("mov.b64 {%0, %1}, %2;" : "=f"(lo), "=f"(hi) : "l"(v));
}
__device__ __forceinline__ void fma2(ull& d, ull a, ull b) {
    asm("fma.rn.f32x2 %0, %1, %2, %0;" : "+l"(d) : "l"(a), "l"(b));
}
__device__ __forceinline__ ull add2(ull a, ull b) {
    ull r; asm("add.rn.f32x2 %0, %1, %2;" : "=l"(r) : "l"(a), "l"(b)); return r;
}

// ---------------------------------------------------------------------------
// Initial causal conv: K=32, 64 -> 128, dilation 1.  128 thr, 8x8 tile.
__global__ void __launch_bounds__(128, 2) init_kernel(
    const float* __restrict__ X, const float* __restrict__ W,
    const float* __restrict__ B, float* __restrict__ res_out)
{
    extern __shared__ float sm[];
    float* xt = sm;             // 96*64 floats (95 rows used)
    float* wb = sm + 96 * 64;   // 64*128 floats
    const int tid  = threadIdx.x;
    const int row0 = blockIdx.x * TM;
    const int batchStart = (row0 / T_LEN) * T_LEN;

    for (int i = tid; i < 95 * 16; i += NT) {
        int r = i >> 4, c4 = i & 15;
        int src = row0 - 31 + r;
        float4 v = make_float4(0.f, 0.f, 0.f, 0.f);
        if (src >= batchStart) v = ((const float4*)(X + (size_t)src * 64))[c4];
        ((float4*)(xt + r * 64))[c4] = v;
    }

    const int ty = tid >> 4, tx = tid & 15;
    const int r0 = ty * 8, c0 = tx * 8;

    ull acc[8][4];
    #pragma unroll
    for (int j = 0; j < 4; j++) {
        ull b = pk2(B[c0 + 2*j], B[c0 + 2*j + 1]);
        #pragma unroll
        for (int rr = 0; rr < 8; rr++) acc[rr][j] = b;
    }

    for (int j = 0; j < 32; j++) {
        __syncthreads();
        const float4* ws = (const float4*)(W + (size_t)j * 64 * 128);
        for (int i = tid; i < 2048; i += NT) ((float4*)wb)[i] = ws[i];
        __syncthreads();
        #pragma unroll 2
        for (int kk = 0; kk < 64; kk += 2) {
            float2 ap[8];
            #pragma unroll
            for (int rr = 0; rr < 8; rr++)
                ap[rr] = *(const float2*)(xt + (r0 + rr + j) * 64 + kk);
            #pragma unroll
            for (int q = 0; q < 2; q++) {
                const float* wp = wb + (kk + q) * 128 + c0;
                ulonglong2 wa = *(const ulonglong2*)wp;
                ulonglong2 wc = *(const ulonglong2*)(wp + 4);
                #pragma unroll
                for (int rr = 0; rr < 8; rr++) {
                    float a = q ? ap[rr].y : ap[rr].x;
                    ull ad = pk2(a, a);
                    fma2(acc[rr][0], ad, wa.x);
                    fma2(acc[rr][1], ad, wa.y);
                    fma2(acc[rr][2], ad, wc.x);
                    fma2(acc[rr][3], ad, wc.y);
                }
            }
        }
    }
    #pragma unroll
    for (int rr = 0; rr < 8; rr++) {
        float o[8];
        #pragma unroll
        for (int j = 0; j < 4; j++) upk2(acc[rr][j], o[2*j], o[2*j+1]);
        float* dst = res_out + (size_t)(row0 + r0 + rr) * RCH + c0;
        ((float4*)dst)[0] = make_float4(o[0], o[1], o[2], o[3]);
        ((float4*)dst)[1] = make_float4(o[4], o[5], o[6], o[7]);
    }
}

// ---------------------------------------------------------------------------
__device__ __forceinline__ void bias_init8(ull acc[8][4], const float* __restrict__ b, int c0) {
    #pragma unroll
    for (int j = 0; j < 4; j++) {
        ull v = pk2(__ldg(b + c0 + 2*j), __ldg(b + c0 + 2*j + 1));
        #pragma unroll
        for (int rr = 0; rr < 8; rr++) acc[rr][j] = v;
    }
}

// acc += A0 @ W0 + A1 @ W1  (8-row x 8-col register tile)
__device__ __forceinline__ void gemm2p8(
    const float* __restrict__ sA0, const float* __restrict__ sA1,
    const float* __restrict__ gW0, const float* __restrict__ gW1,
    float* __restrict__ swb, int r0, int c0, int tid, ull acc[8][4])
{
    for (int kc = 0; kc < RCH; kc += KC) {
        __syncthreads();
        const float4* w0s = (const float4*)(gW0 + kc * RCH);
        const float4* w1s = (const float4*)(gW1 + kc * RCH);
        for (int i = tid; i < (KC * RCH) / 4; i += NT) {
            ((float4*)swb)[i]            = w0s[i];
            ((float4*)(swb + KC*RCH))[i] = w1s[i];
        }
        __syncthreads();
        #pragma unroll 2
        for (int kk = 0; kk < KC; kk += 2) {
            float2 a0p[8], a1p[8];
            #pragma unroll
            for (int rr = 0; rr < 8; rr++) {
                a0p[rr] = *(const float2*)(sA0 + (r0 + rr) * RCH + kc + kk);
                a1p[rr] = *(const float2*)(sA1 + (r0 + rr) * RCH + kc + kk);
            }
            #pragma unroll
            for (int q = 0; q < 2; q++) {
                const float* wp0 = swb + (kk + q) * RCH + c0;
                const float* wp1 = swb + KC*RCH + (kk + q) * RCH + c0;
                ulonglong2 wa = *(const ulonglong2*)wp0;
                ulonglong2 wc = *(const ulonglong2*)(wp0 + 4);
                ulonglong2 va = *(const ulonglong2*)wp1;
                ulonglong2 vc = *(const ulonglong2*)(wp1 + 4);
                #pragma unroll
                for (int rr = 0; rr < 8; rr++) {
                    float a0 = q ? a0p[rr].y : a0p[rr].x;
                    float a1 = q ? a1p[rr].y : a1p[rr].x;
                    ull a0d = pk2(a0, a0);
                    ull a1d = pk2(a1, a1);
                    fma2(acc[rr][0], a0d, wa.x);
                    fma2(acc[rr][1], a0d, wa.y);
                    fma2(acc[rr][2], a0d, wc.x);
                    fma2(acc[rr][3], a0d, wc.y);
                    fma2(acc[rr][0], a1d, va.x);
                    fma2(acc[rr][1], a1d, va.y);
                    fma2(acc[rr][2], a1d, vc.x);
                    fma2(acc[rr][3], a1d, vc.y);
                }
            }
        }
    }
}

// accS += A @ Ws ; accR += A @ Wr (same A, 8x8 tile, both accumulators live)
__device__ __forceinline__ void gemmSR8(
    const float* __restrict__ sA,
    const float* __restrict__ gWs, const float* __restrict__ gWr,
    float* __restrict__ swb, int r0, int c0, int tid,
    ull accS[8][4], ull accR[8][4])
{
    for (int kc = 0; kc < RCH; kc += KC) {
        __syncthreads();
        const float4* wss = (const float4*)(gWs + kc * RCH);
        const float4* wrs = (const float4*)(gWr + kc * RCH);
        for (int i = tid; i < (KC * RCH) / 4; i += NT) {
            ((float4*)swb)[i]            = wss[i];
            ((float4*)(swb + KC*RCH))[i] = wrs[i];
        }
        __syncthreads();
        #pragma unroll 2
        for (int kk = 0; kk < KC; kk += 2) {
            float2 ap[8];
            #pragma unroll
            for (int rr = 0; rr < 8; rr++)
                ap[rr] = *(const float2*)(sA + (r0 + rr) * RCH + kc + kk);
            #pragma unroll
            for (int q = 0; q < 2; q++) {
                const float* wps = swb + (kk + q) * RCH + c0;
                const float* wpr = swb + KC*RCH + (kk + q) * RCH + c0;
                ulonglong2 sa = *(const ulonglong2*)wps;
                ulonglong2 sc = *(const ulonglong2*)(wps + 4);
                ulonglong2 qa = *(const ulonglong2*)wpr;
                ulonglong2 qc = *(const ulonglong2*)(wpr + 4);
                #pragma unroll
                for (int rr = 0; rr < 8; rr++) {
                    float p = q ? ap[rr].y : ap[rr].x;
                    ull pd = pk2(p, p);
                    fma2(accS[rr][0], pd, sa.x);
                    fma2(accS[rr][1], pd, sa.y);
                    fma2(accS[rr][2], pd, sc.x);
                    fma2(accS[rr][3], pd, sc.y);
                    fma2(accR[rr][0], pd, qa.x);
                    fma2(accR[rr][1], pd, qa.y);
                    fma2(accR[rr][2], pd, qc.x);
                    fma2(accR[rr][3], pd, qc.y);
                }
            }
        }
    }
}

// ---------------------------------------------------------------------------
// One WaveNet layer, fused. 128 threads, 8x8 register tiles.
__global__ void __launch_bounds__(128, 2) layer_kernel(
    const float* __restrict__ res_in, float* __restrict__ res_out,
    float* __restrict__ out_acc,
    const float* __restrict__ fw, const float* __restrict__ fb,
    const float* __restrict__ gw, const float* __restrict__ gb,
    const float* __restrict__ sw, const float* __restrict__ sb,
    const float* __restrict__ rw, const float* __restrict__ rb,
    int d, int first)
{
    extern __shared__ float sm[];
    float* scur  = sm;                 // TM*128
    float* sprev = sm + TM * RCH;      // TM*128 (reused for p)
    float* swb   = sm + 2 * TM * RCH;  // 2*KC*128

    const int tid  = threadIdx.x;
    const int row0 = blockIdx.x * TM;
    const int batchStart = (row0 / T_LEN) * T_LEN;

    {
        const float4* cin = (const float4*)(res_in + (size_t)row0 * RCH);
        for (int i = tid; i < (TM * RCH) / 4; i += NT) ((float4*)scur)[i] = cin[i];
    }
    for (int i = tid; i < (TM * RCH) / 4; i += NT) {
        int r = i >> 5;
        int src = row0 + r - d;
        float4 v = make_float4(0.f, 0.f, 0.f, 0.f);
        if (src >= batchStart) v = ((const float4*)(res_in + (size_t)src * RCH))[i & 31];
        ((float4*)sprev)[i] = v;
    }

    const int ty = tid >> 4, tx = tid & 15;
    const int r0 = ty * 8, c0 = tx * 8;

    ull acc[8][4];

    // f = tanh(prev @ fw0 + cur @ fw1 + fb)  -> registers (fv)
    bias_init8(acc, fb, c0);
    gemm2p8(sprev, scur, fw, fw + RCH*RCH, swb, r0, c0, tid, acc);
    float fv[8][8];
    #pragma unroll
    for (int rr = 0; rr < 8; rr++)
        #pragma unroll
        for (int j = 0; j < 4; j++) {
            float lo, hi; upk2(acc[rr][j], lo, hi);
            fv[rr][2*j]   = tanhf(lo);
            fv[rr][2*j+1] = tanhf(hi);
        }

    // g = sigmoid(...); p = f*g  (in-place into fv)
    bias_init8(acc, gb, c0);
    gemm2p8(sprev, scur, gw, gw + RCH*RCH, swb, r0, c0, tid, acc);
    #pragma unroll
    for (int rr = 0; rr < 8; rr++)
        #pragma unroll
        for (int j = 0; j < 4; j++) {
            float lo, hi; upk2(acc[rr][j], lo, hi);
            fv[rr][2*j]   /= (1.0f + __expf(-lo));
            fv[rr][2*j+1] /= (1.0f + __expf(-hi));
        }
    __syncthreads();   // all reads of sprev done -> overwrite with p
    #pragma unroll
    for (int rr = 0; rr < 8; rr++) {
        float* dst = sprev + (r0 + rr) * RCH + c0;
        ((float4*)dst)[0] = make_float4(fv[rr][0], fv[rr][1], fv[rr][2], fv[rr][3]);
        ((float4*)dst)[1] = make_float4(fv[rr][4], fv[rr][5], fv[rr][6], fv[rr][7]);
    }

    // skip & residual 1x1 convs (both accumulators at once)
    ull accS[8][4], accR[8][4];
    bias_init8(accS, sb, c0);
    bias_init8(accR, rb, c0);
    gemmSR8(sprev, sw, rw, swb, r0, c0, tid, accS, accR);

    #pragma unroll
    for (int rr = 0; rr < 8; rr++) {
        float s8[8], q8[8];
        #pragma unroll
        for (int j = 0; j < 4; j++) {
            upk2(accS[rr][j], s8[2*j], s8[2*j+1]);
            upk2(accR[rr][j], q8[2*j], q8[2*j+1]);
        }
        size_t base = (size_t)(row0 + r0 + rr) * RCH + c0;
        if (first) {
            ((float4*)(out_acc + base))[0] = make_float4(s8[0], s8[1], s8[2], s8[3]);
            ((float4*)(out_acc + base))[1] = make_float4(s8[4], s8[5], s8[6], s8[7]);
        } else {
            float4 o0 = ((float4*)(out_acc + base))[0];
            float4 o1 = ((float4*)(out_acc + base))[1];
            o0.x += s8[0]; o0.y += s8[1]; o0.z += s8[2]; o0.w += s8[3];
            o1.x += s8[4]; o1.y += s8[5]; o1.z += s8[6]; o1.w += s8[7];
            ((float4*)(out_acc + base))[0] = o0;
            ((float4*)(out_acc + base))[1] = o1;
        }
        const float* c = scur + (r0 + rr) * RCH + c0;
        ((float4*)(res_out + base))[0] = make_float4(c[0]+q8[0], c[1]+q8[1], c[2]+q8[2], c[3]+q8[3]);
        ((float4*)(res_out + base))[1] = make_float4(c[4]+q8[4], c[5]+q8[5], c[6]+q8[6], c[7]+q8[7]);
    }
}

// ---------------------------------------------------------------------------
// Post chain: one warp handles TWO rows, packed lo/hi into f32x2 lanes.
__global__ void __launch_bounds__(256) post_kernel(
    const float* __restrict__ out_acc,
    const float* __restrict__ s0w, const float* __restrict__ s0b,
    const float* __restrict__ srw, const float* __restrict__ srb,
    const float* __restrict__ fnw, const float* __restrict__ fnb,
    float* __restrict__ y)
{
    extern __shared__ float sm[];
    float* w0 = sm;            // 128*32
    float* wr = w0 + 4096;     // 31*32*32
    float* wf = wr + 31744;    // 32*256
    float* b0 = wf + 8192;     // 32
    float* br = b0 + 32;       // 31*32
    float* bf = br + 992;      // 256

    const int tid = threadIdx.x;
    for (int i = tid; i < 4096;  i += blockDim.x) w0[i] = s0w[i];
    for (int i = tid; i < 31744; i += blockDim.x) wr[i] = srw[i];
    for (int i = tid; i < 8192;  i += blockDim.x) wf[i] = fnw[i];
    for (int i = tid; i < 32;    i += blockDim.x) b0[i] = s0b[i];
    for (int i = tid; i < 992;   i += blockDim.x) br[i] = srb[i];
    for (int i = tid; i < 256;   i += blockDim.x) bf[i] = fnb[i];
    __syncthreads();

    const int warp = tid >> 5, lane = tid & 31;
    const int nwarp = blockDim.x >> 5;

    for (int pr = blockIdx.x * nwarp + warp; pr < BT / 2; pr += gridDim.x * nwarp) {
        const int rowA = pr * 2, rowB = pr * 2 + 1;
        float4 xa = ((const float4*)(out_acc + (size_t)rowA * RCH))[lane];
        float4 xb = ((const float4*)(out_acc + (size_t)rowB * RCH))[lane];
        xa.x = fmaxf(xa.x, 0.f); xa.y = fmaxf(xa.y, 0.f); xa.z = fmaxf(xa.z, 0.f); xa.w = fmaxf(xa.w, 0.f);
        xb.x = fmaxf(xb.x, 0.f); xb.y = fmaxf(xb.y, 0.f); xb.z = fmaxf(xb.z, 0.f); xb.w = fmaxf(xb.w, 0.f);
        ull xp0 = pk2(xa.x, xb.x), xp1 = pk2(xa.y, xb.y);
        ull xp2 = pk2(xa.z, xb.z), xp3 = pk2(xa.w, xb.w);

        float bb = b0[lane];
        ull h = pk2(bb, bb);
        #pragma unroll
        for (int s = 0; s < 32; s++) {
            ull v0 = __shfl_sync(0xffffffffu, xp0, s);
            ull v1 = __shfl_sync(0xffffffffu, xp1, s);
            ull v2 = __shfl_sync(0xffffffffu, xp2, s);
            ull v3 = __shfl_sync(0xffffffffu, xp3, s);
            float wv0 = w0[(s*4+0)*32 + lane];
            float wv1 = w0[(s*4+1)*32 + lane];
            float wv2 = w0[(s*4+2)*32 + lane];
            float wv3 = w0[(s*4+3)*32 + lane];
            fma2(h, v0, pk2(wv0, wv0));
            fma2(h, v1, pk2(wv1, wv1));
            fma2(h, v2, pk2(wv2, wv2));
            fma2(h, v3, pk2(wv3, wv3));
        }
        for (int li = 0; li < 31; li++) {
            float hl, hh; upk2(h, hl, hh);
            ull rv = pk2(fmaxf(hl, 0.f), fmaxf(hh, 0.f));
            const float* wp = wr + li * 1024;
            float bl = br[li*32 + lane];
            ull ha = pk2(bl, bl);
            ull hb = pk2(0.f, 0.f);
            #pragma unroll
            for (int s = 0; s < 32; s += 2) {
                ull ra  = __shfl_sync(0xffffffffu, rv, s);
                ull rb2 = __shfl_sync(0xffffffffu, rv, s + 1);
                float wA = wp[(s    )*32 + lane];
                float wB = wp[(s + 1)*32 + lane];
                fma2(ha, ra,  pk2(wA, wA));
                fma2(hb, rb2, pk2(wB, wB));
            }
            h = add2(ha, hb);
        }
        float hl, hh; upk2(h, hl, hh);
        ull rv = pk2(fmaxf(hl, 0.f), fmaxf(hh, 0.f));
        ull accP[8];
        #pragma unroll
        for (int u = 0; u < 8; u++) {
            float b = bf[lane*8 + u];
            accP[u] = pk2(b, b);
        }
        #pragma unroll
        for (int s = 0; s < 32; s++) {
            ull rs = __shfl_sync(0xffffffffu, rv, s);
            const float* wp = wf + s*256 + lane*8;
            float4 wq0 = *(const float4*)wp;
            float4 wq1 = *(const float4*)(wp + 4);
            fma2(accP[0], rs, pk2(wq0.x, wq0.x));
            fma2(accP[1], rs, pk2(wq0.y, wq0.y));
            fma2(accP[2], rs, pk2(wq0.z, wq0.z));
            fma2(accP[3], rs, pk2(wq0.w, wq0.w));
            fma2(accP[4], rs, pk2(wq1.x, wq1.x));
            fma2(accP[5], rs, pk2(wq1.y, wq1.y));
            fma2(accP[6], rs, pk2(wq1.z, wq1.z));
            fma2(accP[7], rs, pk2(wq1.w, wq1.w));
        }
        float oa[8], ob[8];
        #pragma unroll
        for (int u = 0; u < 8; u++) upk2(accP[u], oa[u], ob[u]);
        float4* ya = (float4*)(y + (size_t)rowA * 256 + lane * 8);
        ya[0] = make_float4(oa[0], oa[1], oa[2], oa[3]);
        ya[1] = make_float4(oa[4], oa[5], oa[6], oa[7]);
        float4* yb = (float4*)(y + (size_t)rowB * 256 + lane * 8);
        yb[0] = make_float4(ob[0], ob[1], ob[2], ob[3]);
        yb[1] = make_float4(ob[4], ob[5], ob[6], ob[7]);
    }
}

// ---------------------------------------------------------------------------
extern "C" void kernel_launch(void* const* d_in, const int* in_sizes, int n_in,
                              void* d_out, int out_size)
{
    const float* X       = (const float*)d_in[0];
    const float* init_w  = (const float*)d_in[1];
    const float* init_b  = (const float*)d_in[2];
    const float* f_w     = (const float*)d_in[3];
    const float* f_b     = (const float*)d_in[4];
    const float* g_w     = (const float*)d_in[5];
    const float* g_b     = (const float*)d_in[6];
    const float* skip_w  = (const float*)d_in[7];
    const float* skip_b  = (const float*)d_in[8];
    const float* res_w   = (const float*)d_in[9];
    const float* res_b   = (const float*)d_in[10];
    const float* skip0_w = (const float*)d_in[11];
    const float* skip0_b = (const float*)d_in[12];
    const float* skipr_w = (const float*)d_in[13];
    const float* skipr_b = (const float*)d_in[14];
    const float* final_w = (const float*)d_in[15];
    const float* final_b = (const float*)d_in[16];
    float* y = (float*)d_out;

    float *resA, *resB, *outacc;
    cudaGetSymbolAddress((void**)&resA,   g_resA);
    cudaGetSymbolAddress((void**)&resB,   g_resB);
    cudaGetSymbolAddress((void**)&outacc, g_outacc);

    const int INIT_SMEM  = (96*64 + 64*128) * 4;                        // 57344 B
    const int LAYER_SMEM = (2*TM*RCH + 2*KC*RCH) * 4;                   // 98304 B
    const int POST_SMEM  = (4096 + 31744 + 8192 + 32 + 992 + 256) * 4;  // 181248 B
    cudaFuncSetAttribute(init_kernel,  cudaFuncAttributeMaxDynamicSharedMemorySize, INIT_SMEM);
    cudaFuncSetAttribute(layer_kernel, cudaFuncAttributeMaxDynamicSharedMemorySize, LAYER_SMEM);
    cudaFuncSetAttribute(post_kernel,  cudaFuncAttributeMaxDynamicSharedMemorySize, POST_SMEM);

    init_kernel<<<BT / TM, NT, INIT_SMEM>>>(X, init_w, init_b, resA);

    static const int DIL[20] = {1,2,4,8,16,32,64,128,256,512,
                                1,2,4,8,16,32,64,128,256,512};
    for (int i = 0; i < 20; i++) {
        const float* rin  = (i & 1) ? resB : resA;
        float*       rout = (i & 1) ? resA : resB;
        layer_kernel<<<BT / TM, NT, LAYER_SMEM>>>(
            rin, rout, outacc,
            f_w + (size_t)i * 2 * RCH * RCH, f_b + i * RCH,
            g_w + (size_t)i * 2 * RCH * RCH, g_b + i * RCH,
            skip_w + (size_t)i * RCH * RCH,  skip_b + i * RCH,
            res_w + (size_t)i * RCH * RCH,   res_b + i * RCH,
            DIL[i], (i == 0) ? 1 : 0);
    }

    post_kernel<<<1184, 256, POST_SMEM>>>(outacc, skip0_w, skip0_b,
                                          skipr_w, skipr_b, final_w, final_b, y);
}

// round 8
// speedup vs baseline: 1.8425x; 1.3653x over previous
#include <cuda_runtime.h>
#include <cuda_bf16.h>
#include <math.h>
#include <stdint.h>

typedef unsigned long long ull;

#define BT    65536
#define T_LEN 16384
#define RCH   128
#define TM    64
#define NT    128

// ---------------- scratch ---------------------------------------------------
__device__ float g_resA[BT * RCH];
__device__ float g_resB[BT * RCH];
__device__ float g_outacc[BT * RCH];
// prepped weights: bf16 hi/lo K-major tiles [128 n x 64 k] (8192 elems each)
// fg per layer: tile idx = gate*8 + part*4 + chunk(4)
// sr per layer: tile idx = mat*4 + part*2 + chunk(2)
__device__ __nv_bfloat16 g_wfg[20 * 16 * 8192];
__device__ __nv_bfloat16 g_wsr[20 * 8 * 8192];

// ---------------- packed f32x2 helpers (SIMT kernels) -----------------------
__device__ __forceinline__ ull pk2(float lo, float hi) {
    ull r; asm("mov.b64 %0, {%1, %2};" : "=l"(r) : "f"(lo), "f"(hi)); return r;
}
__device__ __forceinline__ void upk2(ull v, float& lo, float& hi) {
    asm("mov.b64 {%0, %1}, %2;" : "=f"(lo), "=f"(hi) : "l"(v));
}
__device__ __forceinline__ void fma2(ull& d, ull a, ull b) {
    asm("fma.rn.f32x2 %0, %1, %2, %0;" : "+l"(d) : "l"(a), "l"(b));
}
__device__ __forceinline__ ull add2(ull a, ull b) {
    ull r; asm("add.rn.f32x2 %0, %1, %2;" : "=l"(r) : "l"(a), "l"(b)); return r;
}

// ---------------- warp-mma helpers ------------------------------------------
__device__ __forceinline__ uint32_t s2u(const void* p) {
    uint32_t a;
    asm("{ .reg .u64 t; cvta.to.shared.u64 t, %1; cvt.u32.u64 %0, t; }" : "=r"(a) : "l"(p));
    return a;
}
__device__ __forceinline__ void ldm4(uint32_t* r, uint32_t addr) {
    asm volatile("ldmatrix.sync.aligned.m8n8.x4.shared.b16 {%0,%1,%2,%3}, [%4];"
                 : "=r"(r[0]), "=r"(r[1]), "=r"(r[2]), "=r"(r[3]) : "r"(addr));
}
__device__ __forceinline__ void mma16816(float* d, const uint32_t* a, uint32_t b0, uint32_t b1) {
    asm volatile("mma.sync.aligned.m16n8k16.row.col.f32.bf16.bf16.f32 "
                 "{%0,%1,%2,%3}, {%4,%5,%6,%7}, {%8,%9}, {%0,%1,%2,%3};"
                 : "+f"(d[0]), "+f"(d[1]), "+f"(d[2]), "+f"(d[3])
                 : "r"(a[0]), "r"(a[1]), "r"(a[2]), "r"(a[3]), "r"(b0), "r"(b1));
}
#define STS128(a, v) \
    asm volatile("st.shared.v4.b32 [%0], {%1,%2,%3,%4};" :: "r"(a), "r"((v).x), "r"((v).y), "r"((v).z), "r"((v).w))
#define STS32(a, v) asm volatile("st.shared.b32 [%0], %1;" :: "r"(a), "r"(v))

// smem layout (bytes): bias[512 f32] | A hi [64x264 bf16] | A lo | W stage 4x[128x72 bf16]
#define SA_STRIDE 528
#define ALO_OFF   33792
#define W_STRIDE  144
#define W_TILE    18432
#define OFF_A     2048
#define OFF_W     (OFF_A + 2 * 33792)     // 69632
#define LSMEM     (OFF_W + 4 * W_TILE)    // 143360

// ---------------------------------------------------------------------------
// Weight prep: split fp32 weights to bf16 hi/lo, transpose to [n][k] tiles.
__global__ void prep_kernel(const float* __restrict__ fw, const float* __restrict__ gw,
                            const float* __restrict__ sw, const float* __restrict__ rw)
{
    const int total_fg = 20 * 2 * 4 * 128 * 64;
    const int total_sr = 20 * 2 * 2 * 128 * 64;
    for (int idx = blockIdx.x * blockDim.x + threadIdx.x; idx < total_fg + total_sr;
         idx += gridDim.x * blockDim.x) {
        if (idx < total_fg) {
            int k = idx & 63, n = (idx >> 6) & 127, c = (idx >> 13) & 3;
            int gate = (idx >> 15) & 1, layer = idx >> 16;
            int kk = c * 64 + k, tap = kk >> 7, kc = kk & 127;
            const float* src = gate ? gw : fw;
            float w = src[(((size_t)layer * 2 + tap) * 128 + kc) * 128 + n];
            __nv_bfloat16 hi = __float2bfloat16(w);
            __nv_bfloat16 lo = __float2bfloat16(w - __bfloat162float(hi));
            size_t tbase = ((size_t)layer * 16 + gate * 8) * 8192 + (size_t)n * 64 + k;
            g_wfg[tbase + (size_t)(0 * 4 + c) * 8192] = hi;
            g_wfg[tbase + (size_t)(1 * 4 + c) * 8192] = lo;
        } else {
            int j = idx - total_fg;
            int k = j & 63, n = (j >> 6) & 127, c = (j >> 13) & 1;
            int mat = (j >> 14) & 1, layer = j >> 15;
            int kc = c * 64 + k;
            const float* src = mat ? rw : sw;
            float w = src[((size_t)layer * 128 + kc) * 128 + n];
            __nv_bfloat16 hi = __float2bfloat16(w);
            __nv_bfloat16 lo = __float2bfloat16(w - __bfloat162float(hi));
            size_t tbase = ((size_t)layer * 8 + mat * 4) * 8192 + (size_t)n * 64 + k;
            g_wsr[tbase + (size_t)(0 * 2 + c) * 8192] = hi;
            g_wsr[tbase + (size_t)(1 * 2 + c) * 8192] = lo;
        }
    }
}

// ---------------------------------------------------------------------------
// Tensor-core (mma.sync) WaveNet layer. 1024 CTAs x 64 rows, 256 thr / 8 warps.
__global__ void __launch_bounds__(256, 1) tlayer_kernel(
    const float* __restrict__ res_in, float* __restrict__ res_out,
    float* __restrict__ out_acc,
    const __nv_bfloat16* __restrict__ wfg, const __nv_bfloat16* __restrict__ wsr,
    const float* __restrict__ fb, const float* __restrict__ gb,
    const float* __restrict__ sb, const float* __restrict__ rb,
    int d, int first)
{
    extern __shared__ char smem[];
    const uint32_t sbase = s2u(smem);
    float* sbias = (float*)smem;
    const uint32_t sA = sbase + OFF_A;
    const uint32_t sW = sbase + OFF_W;

    const int tid = threadIdx.x, wid = tid >> 5, lane = tid & 31;
    const int row0 = blockIdx.x * TM;
    const int batchStart = (row0 / T_LEN) * T_LEN;

    for (int i = tid; i < 512; i += 256) {
        int grp = i >> 7, n = i & 127;
        const float* p = grp == 0 ? fb : grp == 1 ? gb : grp == 2 ? sb : rb;
        sbias[i] = p[n];
    }

    // ---- stage A = [prev(128) | cur(128)] as bf16 hi/lo, row-major [64][264]
    for (int idx = tid; idx < 2048; idx += 256) {
        int row = idx >> 5, ch = (idx & 31) * 8;
        int srow, c2;
        if (ch < 128) { srow = row0 + row - d; c2 = ch; }
        else          { srow = row0 + row;     c2 = ch - 128; }
        float v[8];
        if (srow >= batchStart) {
            const float4* sp = (const float4*)(res_in + (size_t)srow * RCH + c2);
            float4 a = sp[0], b2 = sp[1];
            v[0]=a.x; v[1]=a.y; v[2]=a.z; v[3]=a.w; v[4]=b2.x; v[5]=b2.y; v[6]=b2.z; v[7]=b2.w;
        } else {
            #pragma unroll
            for (int q = 0; q < 8; q++) v[q] = 0.f;
        }
        uint4 hp, lp;
        uint32_t* hw = (uint32_t*)&hp;
        uint32_t* lw = (uint32_t*)&lp;
        #pragma unroll
        for (int q = 0; q < 4; q++) {
            __nv_bfloat16 h0 = __float2bfloat16(v[2*q]),   h1 = __float2bfloat16(v[2*q+1]);
            __nv_bfloat16 l0 = __float2bfloat16(v[2*q]   - __bfloat162float(h0));
            __nv_bfloat16 l1 = __float2bfloat16(v[2*q+1] - __bfloat162float(h1));
            hw[q] = (uint32_t)__bfloat16_as_ushort(h0) | ((uint32_t)__bfloat16_as_ushort(h1) << 16);
            lw[q] = (uint32_t)__bfloat16_as_ushort(l0) | ((uint32_t)__bfloat16_as_ushort(l1) << 16);
        }
        uint32_t dst = sA + row * SA_STRIDE + ch * 2;
        STS128(dst, hp);
        STS128(dst + ALO_OFF, lp);
    }
    __syncthreads();

    // ldmatrix lane addressing
    const int mbase = (wid & 1) * 32;
    const int nbase = (wid >> 1) * 32;
    const int aRow = lane & 15, aCol = (lane >> 4) * 8;
    const int bm = lane >> 3;
    const int bRow = (lane & 7) + ((bm >> 1) * 8), bCol = (bm & 1) * 8;
    const uint32_t aBase = sA + (mbase + aRow) * SA_STRIDE + aCol * 2;   // + mt*16*528 + kA*2 (+ALO_OFF)
    const uint32_t bBase = sW + (nbase + bRow) * W_STRIDE + bCol * 2;    // + j*W_TILE + nt*16*144 + kW*2

    float accf[2][4][4], accg[2][4][4];
    #pragma unroll
    for (int mt = 0; mt < 2; mt++)
        #pragma unroll
        for (int nq = 0; nq < 4; nq++)
            #pragma unroll
            for (int q = 0; q < 4; q++) { accf[mt][nq][q] = 0.f; accg[mt][nq][q] = 0.f; }

    // ---- f/g GEMMs: K = 256, 4 chunks of 64
    for (int c = 0; c < 4; c++) {
        for (int i = tid; i < 4096; i += 256) {
            int j = i >> 10, u = i & 1023, n = u >> 3, ku = u & 7;
            const __nv_bfloat16* src = wfg + ((size_t)((j >> 1) * 8 + (j & 1) * 4 + c)) * 8192
                                          + (size_t)n * 64 + ku * 8;
            uint4 v = *(const uint4*)src;
            STS128(sW + j * W_TILE + n * W_STRIDE + ku * 16, v);
        }
        __syncthreads();
        #pragma unroll
        for (int ks = 0; ks < 4; ks++) {
            const int kA2 = (c * 64 + ks * 16) * 2, kW2 = ks * 16 * 2;
            uint32_t ah[2][4], al[2][4];
            ldm4(ah[0], aBase + kA2);
            ldm4(ah[1], aBase + 16 * SA_STRIDE + kA2);
            ldm4(al[0], aBase + ALO_OFF + kA2);
            ldm4(al[1], aBase + ALO_OFF + 16 * SA_STRIDE + kA2);
            uint32_t bh[2][4], bl[2][4];
            ldm4(bh[0], bBase + 0 * W_TILE + kW2);
            ldm4(bh[1], bBase + 0 * W_TILE + 16 * W_STRIDE + kW2);
            ldm4(bl[0], bBase + 1 * W_TILE + kW2);
            ldm4(bl[1], bBase + 1 * W_TILE + 16 * W_STRIDE + kW2);
            #pragma unroll
            for (int mt = 0; mt < 2; mt++)
                #pragma unroll
                for (int nq = 0; nq < 4; nq++) {
                    int nt = nq >> 1, pr = (nq & 1) * 2;
                    mma16816(accf[mt][nq], ah[mt], bh[nt][pr], bh[nt][pr + 1]);
                    mma16816(accf[mt][nq], ah[mt], bl[nt][pr], bl[nt][pr + 1]);
                    mma16816(accf[mt][nq], al[mt], bh[nt][pr], bh[nt][pr + 1]);
                }
            ldm4(bh[0], bBase + 2 * W_TILE + kW2);
            ldm4(bh[1], bBase + 2 * W_TILE + 16 * W_STRIDE + kW2);
            ldm4(bl[0], bBase + 3 * W_TILE + kW2);
            ldm4(bl[1], bBase + 3 * W_TILE + 16 * W_STRIDE + kW2);
            #pragma unroll
            for (int mt = 0; mt < 2; mt++)
                #pragma unroll
                for (int nq = 0; nq < 4; nq++) {
                    int nt = nq >> 1, pr = (nq & 1) * 2;
                    mma16816(accg[mt][nq], ah[mt], bh[nt][pr], bh[nt][pr + 1]);
                    mma16816(accg[mt][nq], ah[mt], bl[nt][pr], bl[nt][pr + 1]);
                    mma16816(accg[mt][nq], al[mt], bh[nt][pr], bh[nt][pr + 1]);
                }
        }
        __syncthreads();
    }

    // ---- gate epilogue: p = tanh(f+fb)*sigmoid(g+gb) -> hi/lo into A buffer
    const int qrow = lane >> 2, qcol = (lane & 3) * 2;
    #pragma unroll
    for (int mt = 0; mt < 2; mt++)
        #pragma unroll
        for (int nq = 0; nq < 4; nq++)
            #pragma unroll
            for (int rp = 0; rp < 2; rp++) {
                int row = mbase + mt * 16 + qrow + rp * 8;
                int col = nbase + nq * 8 + qcol;
                float f0 = tanhf(accf[mt][nq][rp * 2]     + sbias[col]);
                float f1 = tanhf(accf[mt][nq][rp * 2 + 1] + sbias[col + 1]);
                float g0 = 1.f / (1.f + __expf(-(accg[mt][nq][rp * 2]     + sbias[128 + col])));
                float g1 = 1.f / (1.f + __expf(-(accg[mt][nq][rp * 2 + 1] + sbias[128 + col + 1])));
                float p0 = f0 * g0, p1 = f1 * g1;
                __nv_bfloat16 h0 = __float2bfloat16(p0), h1 = __float2bfloat16(p1);
                __nv_bfloat16 l0 = __float2bfloat16(p0 - __bfloat162float(h0));
                __nv_bfloat16 l1 = __float2bfloat16(p1 - __bfloat162float(h1));
                uint32_t hv = (uint32_t)__bfloat16_as_ushort(h0) | ((uint32_t)__bfloat16_as_ushort(h1) << 16);
                uint32_t lv = (uint32_t)__bfloat16_as_ushort(l0) | ((uint32_t)__bfloat16_as_ushort(l1) << 16);
                uint32_t dst = sA + row * SA_STRIDE + col * 2;
                STS32(dst, hv);
                STS32(dst + ALO_OFF, lv);
            }
    __syncthreads();

    // ---- skip/res GEMMs: K = 128, 2 chunks
    float accs[2][4][4], accr[2][4][4];
    #pragma unroll
    for (int mt = 0; mt < 2; mt++)
        #pragma unroll
        for (int nq = 0; nq < 4; nq++)
            #pragma unroll
            for (int q = 0; q < 4; q++) { accs[mt][nq][q] = 0.f; accr[mt][nq][q] = 0.f; }

    for (int c = 0; c < 2; c++) {
        for (int i = tid; i < 4096; i += 256) {
            int j = i >> 10, u = i & 1023, n = u >> 3, ku = u & 7;
            const __nv_bfloat16* src = wsr + ((size_t)((j >> 1) * 4 + (j & 1) * 2 + c)) * 8192
                                          + (size_t)n * 64 + ku * 8;
            uint4 v = *(const uint4*)src;
            STS128(sW + j * W_TILE + n * W_STRIDE + ku * 16, v);
        }
        __syncthreads();
        #pragma unroll
        for (int ks = 0; ks < 4; ks++) {
            const int kA2 = (c * 64 + ks * 16) * 2, kW2 = ks * 16 * 2;
            uint32_t ah[2][4], al[2][4];
            ldm4(ah[0], aBase + kA2);
            ldm4(ah[1], aBase + 16 * SA_STRIDE + kA2);
            ldm4(al[0], aBase + ALO_OFF + kA2);
            ldm4(al[1], aBase + ALO_OFF + 16 * SA_STRIDE + kA2);
            uint32_t bh[2][4], bl[2][4];
            ldm4(bh[0], bBase + 0 * W_TILE + kW2);
            ldm4(bh[1], bBase + 0 * W_TILE + 16 * W_STRIDE + kW2);
            ldm4(bl[0], bBase + 1 * W_TILE + kW2);
            ldm4(bl[1], bBase + 1 * W_TILE + 16 * W_STRIDE + kW2);
            #pragma unroll
            for (int mt = 0; mt < 2; mt++)
                #pragma unroll
                for (int nq = 0; nq < 4; nq++) {
                    int nt = nq >> 1, pr = (nq & 1) * 2;
                    mma16816(accs[mt][nq], ah[mt], bh[nt][pr], bh[nt][pr + 1]);
                    mma16816(accs[mt][nq], ah[mt], bl[nt][pr], bl[nt][pr + 1]);
                    mma16816(accs[mt][nq], al[mt], bh[nt][pr], bh[nt][pr + 1]);
                }
            ldm4(bh[0], bBase + 2 * W_TILE + kW2);
            ldm4(bh[1], bBase + 2 * W_TILE + 16 * W_STRIDE + kW2);
            ldm4(bl[0], bBase + 3 * W_TILE + kW2);
            ldm4(bl[1], bBase + 3 * W_TILE + 16 * W_STRIDE + kW2);
            #pragma unroll
            for (int mt = 0; mt < 2; mt++)
                #pragma unroll
                for (int nq = 0; nq < 4; nq++) {
                    int nt = nq >> 1, pr = (nq & 1) * 2;
                    mma16816(accr[mt][nq], ah[mt], bh[nt][pr], bh[nt][pr + 1]);
                    mma16816(accr[mt][nq], ah[mt], bl[nt][pr], bl[nt][pr + 1]);
                    mma16816(accr[mt][nq], al[mt], bh[nt][pr], bh[nt][pr + 1]);
                }
        }
        __syncthreads();
    }

    // ---- final epilogue
    #pragma unroll
    for (int mt = 0; mt < 2; mt++)
        #pragma unroll
        for (int nq = 0; nq < 4; nq++)
            #pragma unroll
            for (int rp = 0; rp < 2; rp++) {
                int row = mbase + mt * 16 + qrow + rp * 8;
                int col = nbase + nq * 8 + qcol;
                int grow = row0 + row;
                float s0 = accs[mt][nq][rp * 2]     + sbias[256 + col];
                float s1 = accs[mt][nq][rp * 2 + 1] + sbias[256 + col + 1];
                float* oa = out_acc + (size_t)grow * RCH + col;
                if (!first) {
                    float2 oo = *(const float2*)oa;
                    s0 += oo.x; s1 += oo.y;
                }
                *(float2*)oa = make_float2(s0, s1);
                float2 rv = *(const float2*)(res_in + (size_t)grow * RCH + col);
                float r0 = rv.x + accr[mt][nq][rp * 2]     + sbias[384 + col];
                float r1 = rv.y + accr[mt][nq][rp * 2 + 1] + sbias[384 + col + 1];
                *(float2*)(res_out + (size_t)grow * RCH + col) = make_float2(r0, r1);
            }
}

// ---------------------------------------------------------------------------
// Initial causal conv: K=32, 64 -> 128, dilation 1.  128 thr, 8x8 tile. (SIMT)
__global__ void __launch_bounds__(128, 2) init_kernel(
    const float* __restrict__ X, const float* __restrict__ W,
    const float* __restrict__ B, float* __restrict__ res_out)
{
    extern __shared__ float sm[];
    float* xt = sm;
    float* wb = sm + 96 * 64;
    const int tid  = threadIdx.x;
    const int row0 = blockIdx.x * TM;
    const int batchStart = (row0 / T_LEN) * T_LEN;

    for (int i = tid; i < 95 * 16; i += NT) {
        int r = i >> 4, c4 = i & 15;
        int src = row0 - 31 + r;
        float4 v = make_float4(0.f, 0.f, 0.f, 0.f);
        if (src >= batchStart) v = ((const float4*)(X + (size_t)src * 64))[c4];
        ((float4*)(xt + r * 64))[c4] = v;
    }

    const int ty = tid >> 4, tx = tid & 15;
    const int r0 = ty * 8, c0 = tx * 8;

    ull acc[8][4];
    #pragma unroll
    for (int j = 0; j < 4; j++) {
        ull b = pk2(B[c0 + 2*j], B[c0 + 2*j + 1]);
        #pragma unroll
        for (int rr = 0; rr < 8; rr++) acc[rr][j] = b;
    }

    for (int j = 0; j < 32; j++) {
        __syncthreads();
        const float4* ws = (const float4*)(W + (size_t)j * 64 * 128);
        for (int i = tid; i < 2048; i += NT) ((float4*)wb)[i] = ws[i];
        __syncthreads();
        #pragma unroll 2
        for (int kk = 0; kk < 64; kk += 2) {
            float2 ap[8];
            #pragma unroll
            for (int rr = 0; rr < 8; rr++)
                ap[rr] = *(const float2*)(xt + (r0 + rr + j) * 64 + kk);
            #pragma unroll
            for (int q = 0; q < 2; q++) {
                const float* wp = wb + (kk + q) * 128 + c0;
                ulonglong2 wa = *(const ulonglong2*)wp;
                ulonglong2 wc = *(const ulonglong2*)(wp + 4);
                #pragma unroll
                for (int rr = 0; rr < 8; rr++) {
                    float a = q ? ap[rr].y : ap[rr].x;
                    ull ad = pk2(a, a);
                    fma2(acc[rr][0], ad, wa.x);
                    fma2(acc[rr][1], ad, wa.y);
                    fma2(acc[rr][2], ad, wc.x);
                    fma2(acc[rr][3], ad, wc.y);
                }
            }
        }
    }
    #pragma unroll
    for (int rr = 0; rr < 8; rr++) {
        float o[8];
        #pragma unroll
        for (int j = 0; j < 4; j++) upk2(acc[rr][j], o[2*j], o[2*j+1]);
        float* dst = res_out + (size_t)(row0 + r0 + rr) * RCH + c0;
        ((float4*)dst)[0] = make_float4(o[0], o[1], o[2], o[3]);
        ((float4*)dst)[1] = make_float4(o[4], o[5], o[6], o[7]);
    }
}

// ---------------------------------------------------------------------------
// Post chain: one warp handles TWO rows, packed lo/hi into f32x2 lanes. (SIMT)
__global__ void __launch_bounds__(256) post_kernel(
    const float* __restrict__ out_acc,
    const float* __restrict__ s0w, const float* __restrict__ s0b,
    const float* __restrict__ srw, const float* __restrict__ srb,
    const float* __restrict__ fnw, const float* __restrict__ fnb,
    float* __restrict__ y)
{
    extern __shared__ float sm[];
    float* w0 = sm;
    float* wr = w0 + 4096;
    float* wf = wr + 31744;
    float* b0 = wf + 8192;
    float* br = b0 + 32;
    float* bf = br + 992;

    const int tid = threadIdx.x;
    for (int i = tid; i < 4096;  i += blockDim.x) w0[i] = s0w[i];
    for (int i = tid; i < 31744; i += blockDim.x) wr[i] = srw[i];
    for (int i = tid; i < 8192;  i += blockDim.x) wf[i] = fnw[i];
    for (int i = tid; i < 32;    i += blockDim.x) b0[i] = s0b[i];
    for (int i = tid; i < 992;   i += blockDim.x) br[i] = srb[i];
    for (int i = tid; i < 256;   i += blockDim.x) bf[i] = fnb[i];
    __syncthreads();

    const int warp = tid >> 5, lane = tid & 31;
    const int nwarp = blockDim.x >> 5;

    for (int pr = blockIdx.x * nwarp + warp; pr < BT / 2; pr += gridDim.x * nwarp) {
        const int rowA = pr * 2, rowB = pr * 2 + 1;
        float4 xa = ((const float4*)(out_acc + (size_t)rowA * RCH))[lane];
        float4 xb = ((const float4*)(out_acc + (size_t)rowB * RCH))[lane];
        xa.x = fmaxf(xa.x, 0.f); xa.y = fmaxf(xa.y, 0.f); xa.z = fmaxf(xa.z, 0.f); xa.w = fmaxf(xa.w, 0.f);
        xb.x = fmaxf(xb.x, 0.f); xb.y = fmaxf(xb.y, 0.f); xb.z = fmaxf(xb.z, 0.f); xb.w = fmaxf(xb.w, 0.f);
        ull xp0 = pk2(xa.x, xb.x), xp1 = pk2(xa.y, xb.y);
        ull xp2 = pk2(xa.z, xb.z), xp3 = pk2(xa.w, xb.w);

        float bb = b0[lane];
        ull h = pk2(bb, bb);
        #pragma unroll
        for (int s = 0; s < 32; s++) {
            ull v0 = __shfl_sync(0xffffffffu, xp0, s);
            ull v1 = __shfl_sync(0xffffffffu, xp1, s);
            ull v2 = __shfl_sync(0xffffffffu, xp2, s);
            ull v3 = __shfl_sync(0xffffffffu, xp3, s);
            float wv0 = w0[(s*4+0)*32 + lane];
            float wv1 = w0[(s*4+1)*32 + lane];
            float wv2 = w0[(s*4+2)*32 + lane];
            float wv3 = w0[(s*4+3)*32 + lane];
            fma2(h, v0, pk2(wv0, wv0));
            fma2(h, v1, pk2(wv1, wv1));
            fma2(h, v2, pk2(wv2, wv2));
            fma2(h, v3, pk2(wv3, wv3));
        }
        for (int li = 0; li < 31; li++) {
            float hl, hh; upk2(h, hl, hh);
            ull rv = pk2(fmaxf(hl, 0.f), fmaxf(hh, 0.f));
            const float* wp = wr + li * 1024;
            float bl = br[li*32 + lane];
            ull ha = pk2(bl, bl);
            ull hb = pk2(0.f, 0.f);
            #pragma unroll
            for (int s = 0; s < 32; s += 2) {
                ull ra  = __shfl_sync(0xffffffffu, rv, s);
                ull rb2 = __shfl_sync(0xffffffffu, rv, s + 1);
                float wA = wp[(s    )*32 + lane];
                float wB = wp[(s + 1)*32 + lane];
                fma2(ha, ra,  pk2(wA, wA));
                fma2(hb, rb2, pk2(wB, wB));
            }
            h = add2(ha, hb);
        }
        float hl, hh; upk2(h, hl, hh);
        ull rv = pk2(fmaxf(hl, 0.f), fmaxf(hh, 0.f));
        ull accP[8];
        #pragma unroll
        for (int u = 0; u < 8; u++) {
            float b = bf[lane*8 + u];
            accP[u] = pk2(b, b);
        }
        #pragma unroll
        for (int s = 0; s < 32; s++) {
            ull rs = __shfl_sync(0xffffffffu, rv, s);
            const float* wp = wf + s*256 + lane*8;
            float4 wq0 = *(const float4*)wp;
            float4 wq1 = *(const float4*)(wp + 4);
            fma2(accP[0], rs, pk2(wq0.x, wq0.x));
            fma2(accP[1], rs, pk2(wq0.y, wq0.y));
            fma2(accP[2], rs, pk2(wq0.z, wq0.z));
            fma2(accP[3], rs, pk2(wq0.w, wq0.w));
            fma2(accP[4], rs, pk2(wq1.x, wq1.x));
            fma2(accP[5], rs, pk2(wq1.y, wq1.y));
            fma2(accP[6], rs, pk2(wq1.z, wq1.z));
            fma2(accP[7], rs, pk2(wq1.w, wq1.w));
        }
        float oa[8], ob[8];
        #pragma unroll
        for (int u = 0; u < 8; u++) upk2(accP[u], oa[u], ob[u]);
        float4* ya = (float4*)(y + (size_t)rowA * 256 + lane * 8);
        ya[0] = make_float4(oa[0], oa[1], oa[2], oa[3]);
        ya[1] = make_float4(oa[4], oa[5], oa[6], oa[7]);
        float4* yb = (float4*)(y + (size_t)rowB * 256 + lane * 8);
        yb[0] = make_float4(ob[0], ob[1], ob[2], ob[3]);
        yb[1] = make_float4(ob[4], ob[5], ob[6], ob[7]);
    }
}

// ---------------------------------------------------------------------------
extern "C" void kernel_launch(void* const* d_in, const int* in_sizes, int n_in,
                              void* d_out, int out_size)
{
    const float* X       = (const float*)d_in[0];
    const float* init_w  = (const float*)d_in[1];
    const float* init_b  = (const float*)d_in[2];
    const float* f_w     = (const float*)d_in[3];
    const float* f_b     = (const float*)d_in[4];
    const float* g_w     = (const float*)d_in[5];
    const float* g_b     = (const float*)d_in[6];
    const float* skip_w  = (const float*)d_in[7];
    const float* skip_b  = (const float*)d_in[8];
    const float* res_w   = (const float*)d_in[9];
    const float* res_b   = (const float*)d_in[10];
    const float* skip0_w = (const float*)d_in[11];
    const float* skip0_b = (const float*)d_in[12];
    const float* skipr_w = (const float*)d_in[13];
    const float* skipr_b = (const float*)d_in[14];
    const float* final_w = (const float*)d_in[15];
    const float* final_b = (const float*)d_in[16];
    float* y = (float*)d_out;

    float *resA, *resB, *outacc;
    __nv_bfloat16 *wfg, *wsr;
    cudaGetSymbolAddress((void**)&resA,   g_resA);
    cudaGetSymbolAddress((void**)&resB,   g_resB);
    cudaGetSymbolAddress((void**)&outacc, g_outacc);
    cudaGetSymbolAddress((void**)&wfg,    g_wfg);
    cudaGetSymbolAddress((void**)&wsr,    g_wsr);

    const int INIT_SMEM  = (96*64 + 64*128) * 4;
    const int POST_SMEM  = (4096 + 31744 + 8192 + 32 + 992 + 256) * 4;
    cudaFuncSetAttribute(init_kernel,   cudaFuncAttributeMaxDynamicSharedMemorySize, INIT_SMEM);
    cudaFuncSetAttribute(tlayer_kernel, cudaFuncAttributeMaxDynamicSharedMemorySize, LSMEM);
    cudaFuncSetAttribute(post_kernel,   cudaFuncAttributeMaxDynamicSharedMemorySize, POST_SMEM);

    prep_kernel<<<2048, 256>>>(f_w, g_w, skip_w, res_w);
    init_kernel<<<BT / TM, NT, INIT_SMEM>>>(X, init_w, init_b, resA);

    static const int DIL[20] = {1,2,4,8,16,32,64,128,256,512,
                                1,2,4,8,16,32,64,128,256,512};
    for (int i = 0; i < 20; i++) {
        const float* rin  = (i & 1) ? resB : resA;
        float*       rout = (i & 1) ? resA : resB;
        tlayer_kernel<<<BT / TM, 256, LSMEM>>>(
            rin, rout, outacc,
            wfg + (size_t)i * 16 * 8192, wsr + (size_t)i * 8 * 8192,
            f_b + i * RCH, g_b + i * RCH, skip_b + i * RCH, res_b + i * RCH,
            DIL[i], (i == 0) ? 1 : 0);
    }

    post_kernel<<<1184, 256, POST_SMEM>>>(outacc, skip0_w, skip0_b,
                                          skipr_w, skipr_b, final_w, final_b, y);
}

// round 10
// speedup vs baseline: 1.9707x; 1.0696x over previous
#include <cuda_runtime.h>
#include <cuda_bf16.h>
#include <math.h>
#include <stdint.h>

typedef unsigned long long ull;

#define BT    65536
#define T_LEN 16384
#define RCH   128
#define TM    64
#define NT    128

// ---------------- scratch ---------------------------------------------------
__device__ float g_resA[BT * RCH];
__device__ float g_resB[BT * RCH];
__device__ float g_outacc[BT * RCH];
// prepped weights: bf16 hi/lo K-major tiles [128 n x 64 k] (8192 elems each)
// fg per layer: tile idx = gate*8 + part*4 + chunk(4)
// sr per layer: tile idx = mat*4 + part*2 + chunk(2)
__device__ __nv_bfloat16 g_wfg[20 * 16 * 8192];
__device__ __nv_bfloat16 g_wsr[20 * 8 * 8192];

// ---------------- packed f32x2 helpers (SIMT kernels) -----------------------
__device__ __forceinline__ ull pk2(float lo, float hi) {
    ull r; asm("mov.b64 %0, {%1, %2};" : "=l"(r) : "f"(lo), "f"(hi)); return r;
}
__device__ __forceinline__ void upk2(ull v, float& lo, float& hi) {
    asm("mov.b64 {%0, %1}, %2;" : "=f"(lo), "=f"(hi) : "l"(v));
}
__device__ __forceinline__ void fma2(ull& d, ull a, ull b) {
    asm("fma.rn.f32x2 %0, %1, %2, %0;" : "+l"(d) : "l"(a), "l"(b));
}
__device__ __forceinline__ ull add2(ull a, ull b) {
    ull r; asm("add.rn.f32x2 %0, %1, %2;" : "=l"(r) : "l"(a), "l"(b)); return r;
}

// ---------------- warp-mma helpers ------------------------------------------
__device__ __forceinline__ uint32_t s2u(const void* p) {
    uint32_t a;
    asm("{ .reg .u64 t; cvta.to.shared.u64 t, %1; cvt.u32.u64 %0, t; }" : "=r"(a) : "l"(p));
    return a;
}
__device__ __forceinline__ void ldm4(uint32_t* r, uint32_t addr) {
    asm volatile("ldmatrix.sync.aligned.m8n8.x4.shared.b16 {%0,%1,%2,%3}, [%4];"
                 : "=r"(r[0]), "=r"(r[1]), "=r"(r[2]), "=r"(r[3]) : "r"(addr));
}
__device__ __forceinline__ void mma16816(float* d, const uint32_t* a, uint32_t b0, uint32_t b1) {
    asm volatile("mma.sync.aligned.m16n8k16.row.col.f32.bf16.bf16.f32 "
                 "{%0,%1,%2,%3}, {%4,%5,%6,%7}, {%8,%9}, {%0,%1,%2,%3};"
                 : "+f"(d[0]), "+f"(d[1]), "+f"(d[2]), "+f"(d[3])
                 : "r"(a[0]), "r"(a[1]), "r"(a[2]), "r"(a[3]), "r"(b0), "r"(b1));
}
#define STS128(a, v) \
    asm volatile("st.shared.v4.b32 [%0], {%1,%2,%3,%4};" :: "r"(a), "r"((v).x), "r"((v).y), "r"((v).z), "r"((v).w))
#define STS32(a, v) asm volatile("st.shared.b32 [%0], %1;" :: "r"(a), "r"(v))
#define CP_ASYNC16(d, s) asm volatile("cp.async.cg.shared.global [%0], [%1], 16;" :: "r"(d), "l"(s))
#define CP_COMMIT()      asm volatile("cp.async.commit_group;" ::: "memory")
#define CP_WAIT_ALL()    asm volatile("cp.async.wait_all;" ::: "memory")

// smem layout (bytes): bias[512 f32] | A hi [64x264 bf16] | A lo | W: 2 buffers x 2 tiles
#define SA_STRIDE 528
#define ALO_OFF   33792
#define W_STRIDE  144
#define W_TILE    18432
#define W_BUF     (2 * W_TILE)            // 36864 (hi tile + lo tile)
#define OFF_A     2048
#define OFF_W     (OFF_A + 2 * 33792)     // 69632
#define LSMEM     (OFF_W + 2 * W_BUF)     // 143360

// ---------------------------------------------------------------------------
// Weight prep: split fp32 weights to bf16 hi/lo, transpose to [n][k] tiles.
__global__ void prep_kernel(const float* __restrict__ fw, const float* __restrict__ gw,
                            const float* __restrict__ sw, const float* __restrict__ rw)
{
    const int total_fg = 20 * 2 * 4 * 128 * 64;
    const int total_sr = 20 * 2 * 2 * 128 * 64;
    for (int idx = blockIdx.x * blockDim.x + threadIdx.x; idx < total_fg + total_sr;
         idx += gridDim.x * blockDim.x) {
        if (idx < total_fg) {
            int k = idx & 63, n = (idx >> 6) & 127, c = (idx >> 13) & 3;
            int gate = (idx >> 15) & 1, layer = idx >> 16;
            int kk = c * 64 + k, tap = kk >> 7, kc = kk & 127;
            const float* src = gate ? gw : fw;
            float w = src[(((size_t)layer * 2 + tap) * 128 + kc) * 128 + n];
            __nv_bfloat16 hi = __float2bfloat16(w);
            __nv_bfloat16 lo = __float2bfloat16(w - __bfloat162float(hi));
            size_t tbase = ((size_t)layer * 16 + gate * 8) * 8192 + (size_t)n * 64 + k;
            g_wfg[tbase + (size_t)(0 * 4 + c) * 8192] = hi;
            g_wfg[tbase + (size_t)(1 * 4 + c) * 8192] = lo;
        } else {
            int j = idx - total_fg;
            int k = j & 63, n = (j >> 6) & 127, c = (j >> 13) & 1;
            int mat = (j >> 14) & 1, layer = j >> 15;
            int kc = c * 64 + k;
            const float* src = mat ? rw : sw;
            float w = src[((size_t)layer * 128 + kc) * 128 + n];
            __nv_bfloat16 hi = __float2bfloat16(w);
            __nv_bfloat16 lo = __float2bfloat16(w - __bfloat162float(hi));
            size_t tbase = ((size_t)layer * 8 + mat * 4) * 8192 + (size_t)n * 64 + k;
            g_wsr[tbase + (size_t)(0 * 2 + c) * 8192] = hi;
            g_wsr[tbase + (size_t)(1 * 2 + c) * 8192] = lo;
        }
    }
}

// stage one phase's weights (hi tile + lo tile) into a W buffer via cp.async
__device__ __forceinline__ void stage2(uint32_t dst, const __nv_bfloat16* __restrict__ hi,
                                       const __nv_bfloat16* __restrict__ lo, int tid)
{
    #pragma unroll
    for (int r = 0; r < 8; r++) {
        int i = r * 256 + tid;
        int t = i >> 10, u = i & 1023, n = u >> 3, ku = u & 7;
        const __nv_bfloat16* s = (t ? lo : hi) + (size_t)n * 64 + ku * 8;
        CP_ASYNC16(dst + t * W_TILE + n * W_STRIDE + ku * 16, s);
    }
}

// one pipeline phase of MMAs: acc += A(hi,lo) x W(hi,lo) over k-chunk cc
#define COMPUTE_PHASE(ACC, cc, wbOff) do {                                     \
    _Pragma("unroll")                                                          \
    for (int ks = 0; ks < 4; ks++) {                                           \
        const int kA2 = ((cc) * 64 + ks * 16) * 2, kW2 = ks * 32;              \
        uint32_t ah[2][4], al[2][4], bh[2][4], bl[2][4];                       \
        ldm4(ah[0], aBase + kA2);                                              \
        ldm4(ah[1], aBase + 16 * SA_STRIDE + kA2);                             \
        ldm4(al[0], aBase + ALO_OFF + kA2);                                    \
        ldm4(al[1], aBase + ALO_OFF + 16 * SA_STRIDE + kA2);                   \
        ldm4(bh[0], bB + (wbOff) + kW2);                                       \
        ldm4(bh[1], bB + (wbOff) + 16 * W_STRIDE + kW2);                       \
        ldm4(bl[0], bB + (wbOff) + W_TILE + kW2);                              \
        ldm4(bl[1], bB + (wbOff) + W_TILE + 16 * W_STRIDE + kW2);              \
        _Pragma("unroll")                                                      \
        for (int mt = 0; mt < 2; mt++)                                         \
            _Pragma("unroll")                                                  \
            for (int nq = 0; nq < 4; nq++) {                                   \
                int nt = nq >> 1, pr = (nq & 1) * 2;                           \
                mma16816(ACC[mt][nq], ah[mt], bh[nt][pr], bh[nt][pr + 1]);     \
                mma16816(ACC[mt][nq], ah[mt], bl[nt][pr], bl[nt][pr + 1]);     \
                mma16816(ACC[mt][nq], al[mt], bh[nt][pr], bh[nt][pr + 1]);     \
            }                                                                  \
    }                                                                          \
} while (0)

// ---------------------------------------------------------------------------
// Tensor-core (mma.sync) WaveNet layer with cp.async pipelined weight staging.
__global__ void __launch_bounds__(256, 1) tlayer_kernel(
    const float* __restrict__ res_in, float* __restrict__ res_out,
    float* __restrict__ out_acc,
    const __nv_bfloat16* __restrict__ wfg, const __nv_bfloat16* __restrict__ wsr,
    const float* __restrict__ fb, const float* __restrict__ gb,
    const float* __restrict__ sb, const float* __restrict__ rb,
    int d, int first)
{
    extern __shared__ char smem[];
    const uint32_t sbase = s2u(smem);
    float* sbias = (float*)smem;
    const uint32_t sA = sbase + OFF_A;
    const uint32_t sW = sbase + OFF_W;

    const int tid = threadIdx.x, wid = tid >> 5, lane = tid & 31;
    const int row0 = blockIdx.x * TM;
    const int batchStart = (row0 / T_LEN) * T_LEN;

    // prefetch phase-0 weights (f, chunk 0) while we stage A
    stage2(sW, wfg, wfg + (size_t)4 * 8192, tid);
    CP_COMMIT();

    for (int i = tid; i < 512; i += 256) {
        int grp = i >> 7, n = i & 127;
        const float* p = grp == 0 ? fb : grp == 1 ? gb : grp == 2 ? sb : rb;
        sbias[i] = p[n];
    }

    // ---- stage A = [prev(128) | cur(128)] as bf16 hi/lo, row-major [64][264]
    for (int idx = tid; idx < 2048; idx += 256) {
        int row = idx >> 5, ch = (idx & 31) * 8;
        int srow, c2;
        if (ch < 128) { srow = row0 + row - d; c2 = ch; }
        else          { srow = row0 + row;     c2 = ch - 128; }
        float v[8];
        if (srow >= batchStart) {
            const float4* sp = (const float4*)(res_in + (size_t)srow * RCH + c2);
            float4 a = sp[0], b2 = sp[1];
            v[0]=a.x; v[1]=a.y; v[2]=a.z; v[3]=a.w; v[4]=b2.x; v[5]=b2.y; v[6]=b2.z; v[7]=b2.w;
        } else {
            #pragma unroll
            for (int q = 0; q < 8; q++) v[q] = 0.f;
        }
        uint4 hp, lp;
        uint32_t* hw = (uint32_t*)&hp;
        uint32_t* lw = (uint32_t*)&lp;
        #pragma unroll
        for (int q = 0; q < 4; q++) {
            __nv_bfloat16 h0 = __float2bfloat16(v[2*q]),   h1 = __float2bfloat16(v[2*q+1]);
            __nv_bfloat16 l0 = __float2bfloat16(v[2*q]   - __bfloat162float(h0));
            __nv_bfloat16 l1 = __float2bfloat16(v[2*q+1] - __bfloat162float(h1));
            hw[q] = (uint32_t)__bfloat16_as_ushort(h0) | ((uint32_t)__bfloat16_as_ushort(h1) << 16);
            lw[q] = (uint32_t)__bfloat16_as_ushort(l0) | ((uint32_t)__bfloat16_as_ushort(l1) << 16);
        }
        uint32_t dst = sA + row * SA_STRIDE + ch * 2;
        STS128(dst, hp);
        STS128(dst + ALO_OFF, lp);
    }
    __syncthreads();

    // ldmatrix lane addressing
    const int mbase = (wid & 1) * 32;
    const int nbase = (wid >> 1) * 32;
    const int aRow = lane & 15, aCol = (lane >> 4) * 8;
    const int bm = lane >> 3;
    const int bRow = (lane & 7) + ((bm >> 1) * 8), bCol = (bm & 1) * 8;
    const uint32_t aBase = sA + (mbase + aRow) * SA_STRIDE + aCol * 2;
    const uint32_t bB = sW + (nbase + bRow) * W_STRIDE + bCol * 2;

    const int qrow = lane >> 2, qcol = (lane & 3) * 2;

    // ---- f/g: 8 pipelined phases (chunk c, gate f/g), buffers ping-pong
    {
        float accf[2][4][4], accg[2][4][4];
        #pragma unroll
        for (int mt = 0; mt < 2; mt++)
            #pragma unroll
            for (int nq = 0; nq < 4; nq++)
                #pragma unroll
                for (int q = 0; q < 4; q++) { accf[mt][nq][q] = 0.f; accg[mt][nq][q] = 0.f; }

        for (int p = 0; p < 8; p++) {
            CP_WAIT_ALL();
            __syncthreads();
            if (p < 7) {
                int pn = p + 1, c = pn >> 1, gate = pn & 1;
                stage2(sW + (pn & 1) * W_BUF,
                       wfg + (size_t)(gate * 8 + c) * 8192,
                       wfg + (size_t)(gate * 8 + 4 + c) * 8192, tid);
            } else {
                // prefetch sr phase 0 (skip, chunk 0) -> buffer 0
                stage2(sW, wsr, wsr + (size_t)2 * 8192, tid);
            }
            CP_COMMIT();
            int c = p >> 1;
            uint32_t wbOff = (uint32_t)(p & 1) * W_BUF;
            if (p & 1) COMPUTE_PHASE(accg, c, wbOff);
            else       COMPUTE_PHASE(accf, c, wbOff);
        }
        __syncthreads();   // all warps done reading A before epilogue overwrites it

        // ---- gate epilogue: p = tanh(f+fb)*sigmoid(g+gb) -> hi/lo into A buffer
        #pragma unroll
        for (int mt = 0; mt < 2; mt++)
            #pragma unroll
            for (int nq = 0; nq < 4; nq++)
                #pragma unroll
                for (int rp = 0; rp < 2; rp++) {
                    int row = mbase + mt * 16 + qrow + rp * 8;
                    int col = nbase + nq * 8 + qcol;
                    float f0 = tanhf(accf[mt][nq][rp * 2]     + sbias[col]);
                    float f1 = tanhf(accf[mt][nq][rp * 2 + 1] + sbias[col + 1]);
                    float g0 = 1.f / (1.f + __expf(-(accg[mt][nq][rp * 2]     + sbias[128 + col])));
                    float g1 = 1.f / (1.f + __expf(-(accg[mt][nq][rp * 2 + 1] + sbias[128 + col + 1])));
                    float p0 = f0 * g0, p1 = f1 * g1;
                    __nv_bfloat16 h0 = __float2bfloat16(p0), h1 = __float2bfloat16(p1);
                    __nv_bfloat16 l0 = __float2bfloat16(p0 - __bfloat162float(h0));
                    __nv_bfloat16 l1 = __float2bfloat16(p1 - __bfloat162float(h1));
                    uint32_t hv = (uint32_t)__bfloat16_as_ushort(h0) | ((uint32_t)__bfloat16_as_ushort(h1) << 16);
                    uint32_t lv = (uint32_t)__bfloat16_as_ushort(l0) | ((uint32_t)__bfloat16_as_ushort(l1) << 16);
                    uint32_t dst = sA + row * SA_STRIDE + col * 2;
                    STS32(dst, hv);
                    STS32(dst + ALO_OFF, lv);
                }
    }
    __syncthreads();

    // ---- skip/res: 4 pipelined phases (skip c0, res c0, skip c1, res c1)
    float accs[2][4][4], accr[2][4][4];
    #pragma unroll
    for (int mt = 0; mt < 2; mt++)
        #pragma unroll
        for (int nq = 0; nq < 4; nq++)
            #pragma unroll
            for (int q = 0; q < 4; q++) { accs[mt][nq][q] = 0.f; accr[mt][nq][q] = 0.f; }

    for (int q = 0; q < 4; q++) {
        CP_WAIT_ALL();
        __syncthreads();
        if (q < 3) {
            int qn = q + 1, mat = qn & 1, c = qn >> 1;
            stage2(sW + (qn & 1) * W_BUF,
                   wsr + (size_t)(mat * 4 + c) * 8192,
                   wsr + (size_t)(mat * 4 + 2 + c) * 8192, tid);
            CP_COMMIT();
        }
        int c = q >> 1;
        uint32_t wbOff = (uint32_t)(q & 1) * W_BUF;
        if (q & 1) COMPUTE_PHASE(accr, c, wbOff);
        else       COMPUTE_PHASE(accs, c, wbOff);
    }

    // ---- final epilogue
    #pragma unroll
    for (int mt = 0; mt < 2; mt++)
        #pragma unroll
        for (int nq = 0; nq < 4; nq++)
            #pragma unroll
            for (int rp = 0; rp < 2; rp++) {
                int row = mbase + mt * 16 + qrow + rp * 8;
                int col = nbase + nq * 8 + qcol;
                int grow = row0 + row;
                float s0 = accs[mt][nq][rp * 2]     + sbias[256 + col];
                float s1 = accs[mt][nq][rp * 2 + 1] + sbias[256 + col + 1];
                float* oa = out_acc + (size_t)grow * RCH + col;
                if (!first) {
                    float2 oo = *(const float2*)oa;
                    s0 += oo.x; s1 += oo.y;
                }
                *(float2*)oa = make_float2(s0, s1);
                float2 rv = *(const float2*)(res_in + (size_t)grow * RCH + col);
                float r0 = rv.x + accr[mt][nq][rp * 2]     + sbias[384 + col];
                float r1 = rv.y + accr[mt][nq][rp * 2 + 1] + sbias[384 + col + 1];
                *(float2*)(res_out + (size_t)grow * RCH + col) = make_float2(r0, r1);
            }
}

// ---------------------------------------------------------------------------
// Initial causal conv: K=32, 64 -> 128, dilation 1.  128 thr, 8x8 tile. (SIMT)
__global__ void __launch_bounds__(128, 2) init_kernel(
    const float* __restrict__ X, const float* __restrict__ W,
    const float* __restrict__ B, float* __restrict__ res_out)
{
    extern __shared__ float sm[];
    float* xt = sm;
    float* wb = sm + 96 * 64;
    const int tid  = threadIdx.x;
    const int row0 = blockIdx.x * TM;
    const int batchStart = (row0 / T_LEN) * T_LEN;

    for (int i = tid; i < 95 * 16; i += NT) {
        int r = i >> 4, c4 = i & 15;
        int src = row0 - 31 + r;
        float4 v = make_float4(0.f, 0.f, 0.f, 0.f);
        if (src >= batchStart) v = ((const float4*)(X + (size_t)src * 64))[c4];
        ((float4*)(xt + r * 64))[c4] = v;
    }

    const int ty = tid >> 4, tx = tid & 15;
    const int r0 = ty * 8, c0 = tx * 8;

    ull acc[8][4];
    #pragma unroll
    for (int j = 0; j < 4; j++) {
        ull b = pk2(B[c0 + 2*j], B[c0 + 2*j + 1]);
        #pragma unroll
        for (int rr = 0; rr < 8; rr++) acc[rr][j] = b;
    }

    for (int j = 0; j < 32; j++) {
        __syncthreads();
        const float4* ws = (const float4*)(W + (size_t)j * 64 * 128);
        for (int i = tid; i < 2048; i += NT) ((float4*)wb)[i] = ws[i];
        __syncthreads();
        #pragma unroll 2
        for (int kk = 0; kk < 64; kk += 2) {
            float2 ap[8];
            #pragma unroll
            for (int rr = 0; rr < 8; rr++)
                ap[rr] = *(const float2*)(xt + (r0 + rr + j) * 64 + kk);
            #pragma unroll
            for (int q = 0; q < 2; q++) {
                const float* wp = wb + (kk + q) * 128 + c0;
                ulonglong2 wa = *(const ulonglong2*)wp;
                ulonglong2 wc = *(const ulonglong2*)(wp + 4);
                #pragma unroll
                for (int rr = 0; rr < 8; rr++) {
                    float a = q ? ap[rr].y : ap[rr].x;
                    ull ad = pk2(a, a);
                    fma2(acc[rr][0], ad, wa.x);
                    fma2(acc[rr][1], ad, wa.y);
                    fma2(acc[rr][2], ad, wc.x);
                    fma2(acc[rr][3], ad, wc.y);
                }
            }
        }
    }
    #pragma unroll
    for (int rr = 0; rr < 8; rr++) {
        float o[8];
        #pragma unroll
        for (int j = 0; j < 4; j++) upk2(acc[rr][j], o[2*j], o[2*j+1]);
        float* dst = res_out + (size_t)(row0 + r0 + rr) * RCH + c0;
        ((float4*)dst)[0] = make_float4(o[0], o[1], o[2], o[3]);
        ((float4*)dst)[1] = make_float4(o[4], o[5], o[6], o[7]);
    }
}

// ---------------------------------------------------------------------------
// Post chain: one warp handles TWO rows, packed lo/hi into f32x2 lanes. (SIMT)
__global__ void __launch_bounds__(256) post_kernel(
    const float* __restrict__ out_acc,
    const float* __restrict__ s0w, const float* __restrict__ s0b,
    const float* __restrict__ srw, const float* __restrict__ srb,
    const float* __restrict__ fnw, const float* __restrict__ fnb,
    float* __restrict__ y)
{
    extern __shared__ float sm[];
    float* w0 = sm;
    float* wr = w0 + 4096;
    float* wf = wr + 31744;
    float* b0 = wf + 8192;
    float* br = b0 + 32;
    float* bf = br + 992;

    const int tid = threadIdx.x;
    for (int i = tid; i < 4096;  i += blockDim.x) w0[i] = s0w[i];
    for (int i = tid; i < 31744; i += blockDim.x) wr[i] = srw[i];
    for (int i = tid; i < 8192;  i += blockDim.x) wf[i] = fnw[i];
    for (int i = tid; i < 32;    i += blockDim.x) b0[i] = s0b[i];
    for (int i = tid; i < 992;   i += blockDim.x) br[i] = srb[i];
    for (int i = tid; i < 256;   i += blockDim.x) bf[i] = fnb[i];
    __syncthreads();

    const int warp = tid >> 5, lane = tid & 31;
    const int nwarp = blockDim.x >> 5;

    for (int pr = blockIdx.x * nwarp + warp; pr < BT / 2; pr += gridDim.x * nwarp) {
        const int rowA = pr * 2, rowB = pr * 2 + 1;
        float4 xa = ((const float4*)(out_acc + (size_t)rowA * RCH))[lane];
        float4 xb = ((const float4*)(out_acc + (size_t)rowB * RCH))[lane];
        xa.x = fmaxf(xa.x, 0.f); xa.y = fmaxf(xa.y, 0.f); xa.z = fmaxf(xa.z, 0.f); xa.w = fmaxf(xa.w, 0.f);
        xb.x = fmaxf(xb.x, 0.f); xb.y = fmaxf(xb.y, 0.f); xb.z = fmaxf(xb.z, 0.f); xb.w = fmaxf(xb.w, 0.f);
        ull xp0 = pk2(xa.x, xb.x), xp1 = pk2(xa.y, xb.y);
        ull xp2 = pk2(xa.z, xb.z), xp3 = pk2(xa.w, xb.w);

        float bb = b0[lane];
        ull h = pk2(bb, bb);
        #pragma unroll
        for (int s = 0; s < 32; s++) {
            ull v0 = __shfl_sync(0xffffffffu, xp0, s);
            ull v1 = __shfl_sync(0xffffffffu, xp1, s);
            ull v2 = __shfl_sync(0xffffffffu, xp2, s);
            ull v3 = __shfl_sync(0xffffffffu, xp3, s);
            float wv0 = w0[(s*4+0)*32 + lane];
            float wv1 = w0[(s*4+1)*32 + lane];
            float wv2 = w0[(s*4+2)*32 + lane];
            float wv3 = w0[(s*4+3)*32 + lane];
            fma2(h, v0, pk2(wv0, wv0));
            fma2(h, v1, pk2(wv1, wv1));
            fma2(h, v2, pk2(wv2, wv2));
            fma2(h, v3, pk2(wv3, wv3));
        }
        for (int li = 0; li < 31; li++) {
            float hl, hh; upk2(h, hl, hh);
            ull rv = pk2(fmaxf(hl, 0.f), fmaxf(hh, 0.f));
            const float* wp = wr + li * 1024;
            float bl = br[li*32 + lane];
            ull ha = pk2(bl, bl);
            ull hb = pk2(0.f, 0.f);
            #pragma unroll
            for (int s = 0; s < 32; s += 2) {
                ull ra  = __shfl_sync(0xffffffffu, rv, s);
                ull rb2 = __shfl_sync(0xffffffffu, rv, s + 1);
                float wA = wp[(s    )*32 + lane];
                float wB = wp[(s + 1)*32 + lane];
                fma2(ha, ra,  pk2(wA, wA));
                fma2(hb, rb2, pk2(wB, wB));
            }
            h = add2(ha, hb);
        }
        float hl, hh; upk2(h, hl, hh);
        ull rv = pk2(fmaxf(hl, 0.f), fmaxf(hh, 0.f));
        ull accP[8];
        #pragma unroll
        for (int u = 0; u < 8; u++) {
            float b = bf[lane*8 + u];
            accP[u] = pk2(b, b);
        }
        #pragma unroll
        for (int s = 0; s < 32; s++) {
            ull rs = __shfl_sync(0xffffffffu, rv, s);
            const float* wp = wf + s*256 + lane*8;
            float4 wq0 = *(const float4*)wp;
            float4 wq1 = *(const float4*)(wp + 4);
            fma2(accP[0], rs, pk2(wq0.x, wq0.x));
            fma2(accP[1], rs, pk2(wq0.y, wq0.y));
            fma2(accP[2], rs, pk2(wq0.z, wq0.z));
            fma2(accP[3], rs, pk2(wq0.w, wq0.w));
            fma2(accP[4], rs, pk2(wq1.x, wq1.x));
            fma2(accP[5], rs, pk2(wq1.y, wq1.y));
            fma2(accP[6], rs, pk2(wq1.z, wq1.z));
            fma2(accP[7], rs, pk2(wq1.w, wq1.w));
        }
        float oa[8], ob[8];
        #pragma unroll
        for (int u = 0; u < 8; u++) upk2(accP[u], oa[u], ob[u]);
        float4* ya = (float4*)(y + (size_t)rowA * 256 + lane * 8);
        ya[0] = make_float4(oa[0], oa[1], oa[2], oa[3]);
        ya[1] = make_float4(oa[4], oa[5], oa[6], oa[7]);
        float4* yb = (float4*)(y + (size_t)rowB * 256 + lane * 8);
        yb[0] = make_float4(ob[0], ob[1], ob[2], ob[3]);
        yb[1] = make_float4(ob[4], ob[5], ob[6], ob[7]);
    }
}

// ---------------------------------------------------------------------------
extern "C" void kernel_launch(void* const* d_in, const int* in_sizes, int n_in,
                              void* d_out, int out_size)
{
    const float* X       = (const float*)d_in[0];
    const float* init_w  = (const float*)d_in[1];
    const float* init_b  = (const float*)d_in[2];
    const float* f_w     = (const float*)d_in[3];
    const float* f_b     = (const float*)d_in[4];
    const float* g_w     = (const float*)d_in[5];
    const float* g_b     = (const float*)d_in[6];
    const float* skip_w  = (const float*)d_in[7];
    const float* skip_b  = (const float*)d_in[8];
    const float* res_w   = (const float*)d_in[9];
    const float* res_b   = (const float*)d_in[10];
    const float* skip0_w = (const float*)d_in[11];
    const float* skip0_b = (const float*)d_in[12];
    const float* skipr_w = (const float*)d_in[13];
    const float* skipr_b = (const float*)d_in[14];
    const float* final_w = (const float*)d_in[15];
    const float* final_b = (const float*)d_in[16];
    float* y = (float*)d_out;

    float *resA, *resB, *outacc;
    __nv_bfloat16 *wfg, *wsr;
    cudaGetSymbolAddress((void**)&resA,   g_resA);
    cudaGetSymbolAddress((void**)&resB,   g_resB);
    cudaGetSymbolAddress((void**)&outacc, g_outacc);
    cudaGetSymbolAddress((void**)&wfg,    g_wfg);
    cudaGetSymbolAddress((void**)&wsr,    g_wsr);

    const int INIT_SMEM  = (96*64 + 64*128) * 4;
    const int POST_SMEM  = (4096 + 31744 + 8192 + 32 + 992 + 256) * 4;
    cudaFuncSetAttribute(init_kernel,   cudaFuncAttributeMaxDynamicSharedMemorySize, INIT_SMEM);
    cudaFuncSetAttribute(tlayer_kernel, cudaFuncAttributeMaxDynamicSharedMemorySize, LSMEM);
    cudaFuncSetAttribute(post_kernel,   cudaFuncAttributeMaxDynamicSharedMemorySize, POST_SMEM);

    prep_kernel<<<2048, 256>>>(f_w, g_w, skip_w, res_w);
    init_kernel<<<BT / TM, NT, INIT_SMEM>>>(X, init_w, init_b, resA);

    static const int DIL[20] = {1,2,4,8,16,32,64,128,256,512,
                                1,2,4,8,16,32,64,128,256,512};
    for (int i = 0; i < 20; i++) {
        const float* rin  = (i & 1) ? resB : resA;
        float*       rout = (i & 1) ? resA : resB;
        tlayer_kernel<<<BT / TM, 256, LSMEM>>>(
            rin, rout, outacc,
            wfg + (size_t)i * 16 * 8192, wsr + (size_t)i * 8 * 8192,
            f_b + i * RCH, g_b + i * RCH, skip_b + i * RCH, res_b + i * RCH,
            DIL[i], (i == 0) ? 1 : 0);
    }

    post_kernel<<<1184, 256, POST_SMEM>>>(outacc, skip0_w, skip0_b,
                                          skipr_w, skipr_b, final_w, final_b, y);
}

// round 11
// speedup vs baseline: 2.5148x; 1.2761x over previous
#include <cuda_runtime.h>
#include <cuda_bf16.h>
#include <math.h>
#include <stdint.h>

typedef unsigned long long ull;

#define BT    65536
#define T_LEN 16384
#define RCH   128
#define TM    64
#define NT    128

// ---------------- scratch ---------------------------------------------------
__device__ float g_resA[BT * RCH];
__device__ float g_resB[BT * RCH];
__device__ float g_outacc[BT * RCH];
// prepped weights: bf16 hi/lo K-major tiles [128 n x 64 k] (8192 elems each)
// fg per layer: tile idx = gate*8 + part*4 + chunk(4)
// sr per layer: tile idx = mat*4 + part*2 + chunk(2)
__device__ __nv_bfloat16 g_wfg[20 * 16 * 8192];
__device__ __nv_bfloat16 g_wsr[20 * 8 * 8192];

// ---------------- packed f32x2 helpers (SIMT kernels) -----------------------
__device__ __forceinline__ ull pk2(float lo, float hi) {
    ull r; asm("mov.b64 %0, {%1, %2};" : "=l"(r) : "f"(lo), "f"(hi)); return r;
}
__device__ __forceinline__ void upk2(ull v, float& lo, float& hi) {
    asm("mov.b64 {%0, %1}, %2;" : "=f"(lo), "=f"(hi) : "l"(v));
}
__device__ __forceinline__ void fma2(ull& d, ull a, ull b) {
    asm("fma.rn.f32x2 %0, %1, %2, %0;" : "+l"(d) : "l"(a), "l"(b));
}
__device__ __forceinline__ ull add2(ull a, ull b) {
    ull r; asm("add.rn.f32x2 %0, %1, %2;" : "=l"(r) : "l"(a), "l"(b)); return r;
}

// ---------------- warp-mma helpers ------------------------------------------
__device__ __forceinline__ uint32_t s2u(const void* p) {
    uint32_t a;
    asm("{ .reg .u64 t; cvta.to.shared.u64 t, %1; cvt.u32.u64 %0, t; }" : "=r"(a) : "l"(p));
    return a;
}
__device__ __forceinline__ void ldm4(uint32_t* r, uint32_t addr) {
    asm volatile("ldmatrix.sync.aligned.m8n8.x4.shared.b16 {%0,%1,%2,%3}, [%4];"
                 : "=r"(r[0]), "=r"(r[1]), "=r"(r[2]), "=r"(r[3]) : "r"(addr));
}
__device__ __forceinline__ void mma16816(float* d, const uint32_t* a, uint32_t b0, uint32_t b1) {
    asm volatile("mma.sync.aligned.m16n8k16.row.col.f32.bf16.bf16.f32 "
                 "{%0,%1,%2,%3}, {%4,%5,%6,%7}, {%8,%9}, {%0,%1,%2,%3};"
                 : "+f"(d[0]), "+f"(d[1]), "+f"(d[2]), "+f"(d[3])
                 : "r"(a[0]), "r"(a[1]), "r"(a[2]), "r"(a[3]), "r"(b0), "r"(b1));
}
#define STS128(a, v) \
    asm volatile("st.shared.v4.b32 [%0], {%1,%2,%3,%4};" :: "r"(a), "r"((v).x), "r"((v).y), "r"((v).z), "r"((v).w))
#define STS32(a, v) asm volatile("st.shared.b32 [%0], %1;" :: "r"(a), "r"(v))
#define CP_ASYNC16(d, s) asm volatile("cp.async.cg.shared.global [%0], [%1], 16;" :: "r"(d), "l"(s))
#define CP_COMMIT()      asm volatile("cp.async.commit_group;" ::: "memory")
#define CP_WAIT_ALL()    asm volatile("cp.async.wait_all;" ::: "memory")

// smem layout (bytes): bias[512 f32] | A hi [64x264 bf16] | A lo | W: 1 buffer x 2 tiles
#define SA_STRIDE 528
#define ALO_OFF   33792
#define W_STRIDE  144
#define W_TILE    18432
#define OFF_A     2048
#define OFF_W     (OFF_A + 2 * 33792)     // 69632
#define LSMEM     (OFF_W + 2 * W_TILE)    // 106496  -> 2 CTAs/SM

// ---------------------------------------------------------------------------
// Weight prep: split fp32 weights to bf16 hi/lo, transpose to [n][k] tiles.
__global__ void prep_kernel(const float* __restrict__ fw, const float* __restrict__ gw,
                            const float* __restrict__ sw, const float* __restrict__ rw)
{
    const int total_fg = 20 * 2 * 4 * 128 * 64;
    const int total_sr = 20 * 2 * 2 * 128 * 64;
    for (int idx = blockIdx.x * blockDim.x + threadIdx.x; idx < total_fg + total_sr;
         idx += gridDim.x * blockDim.x) {
        if (idx < total_fg) {
            int k = idx & 63, n = (idx >> 6) & 127, c = (idx >> 13) & 3;
            int gate = (idx >> 15) & 1, layer = idx >> 16;
            int kk = c * 64 + k, tap = kk >> 7, kc = kk & 127;
            const float* src = gate ? gw : fw;
            float w = src[(((size_t)layer * 2 + tap) * 128 + kc) * 128 + n];
            __nv_bfloat16 hi = __float2bfloat16(w);
            __nv_bfloat16 lo = __float2bfloat16(w - __bfloat162float(hi));
            size_t tbase = ((size_t)layer * 16 + gate * 8) * 8192 + (size_t)n * 64 + k;
            g_wfg[tbase + (size_t)(0 * 4 + c) * 8192] = hi;
            g_wfg[tbase + (size_t)(1 * 4 + c) * 8192] = lo;
        } else {
            int j = idx - total_fg;
            int k = j & 63, n = (j >> 6) & 127, c = (j >> 13) & 1;
            int mat = (j >> 14) & 1, layer = j >> 15;
            int kc = c * 64 + k;
            const float* src = mat ? rw : sw;
            float w = src[((size_t)layer * 128 + kc) * 128 + n];
            __nv_bfloat16 hi = __float2bfloat16(w);
            __nv_bfloat16 lo = __float2bfloat16(w - __bfloat162float(hi));
            size_t tbase = ((size_t)layer * 8 + mat * 4) * 8192 + (size_t)n * 64 + k;
            g_wsr[tbase + (size_t)(0 * 2 + c) * 8192] = hi;
            g_wsr[tbase + (size_t)(1 * 2 + c) * 8192] = lo;
        }
    }
}

// stage one phase's weights (hi tile + lo tile) into the W buffer via cp.async
__device__ __forceinline__ void stage2(uint32_t dst, const __nv_bfloat16* __restrict__ hi,
                                       const __nv_bfloat16* __restrict__ lo, int tid)
{
    #pragma unroll
    for (int r = 0; r < 8; r++) {
        int i = r * 256 + tid;
        int t = i >> 10, u = i & 1023, n = u >> 3, ku = u & 7;
        const __nv_bfloat16* s = (t ? lo : hi) + (size_t)n * 64 + ku * 8;
        CP_ASYNC16(dst + t * W_TILE + n * W_STRIDE + ku * 16, s);
    }
}

// one phase of MMAs: acc += A(hi,lo) x W(hi,lo) over k-chunk cc
#define COMPUTE_PHASE(ACC, cc) do {                                            \
    _Pragma("unroll")                                                          \
    for (int ks = 0; ks < 4; ks++) {                                           \
        const int kA2 = ((cc) * 64 + ks * 16) * 2, kW2 = ks * 32;              \
        uint32_t ah[2][4], al[2][4], bh[2][4], bl[2][4];                       \
        ldm4(ah[0], aBase + kA2);                                              \
        ldm4(ah[1], aBase + 16 * SA_STRIDE + kA2);                             \
        ldm4(al[0], aBase + ALO_OFF + kA2);                                    \
        ldm4(al[1], aBase + ALO_OFF + 16 * SA_STRIDE + kA2);                   \
        ldm4(bh[0], bB + kW2);                                                 \
        ldm4(bh[1], bB + 16 * W_STRIDE + kW2);                                 \
        ldm4(bl[0], bB + W_TILE + kW2);                                        \
        ldm4(bl[1], bB + W_TILE + 16 * W_STRIDE + kW2);                        \
        _Pragma("unroll")                                                      \
        for (int mt = 0; mt < 2; mt++)                                         \
            _Pragma("unroll")                                                  \
            for (int nq = 0; nq < 4; nq++) {                                   \
                int nt = nq >> 1, pr = (nq & 1) * 2;                           \
                mma16816(ACC[mt][nq], ah[mt], bh[nt][pr], bh[nt][pr + 1]);     \
                mma16816(ACC[mt][nq], ah[mt], bl[nt][pr], bl[nt][pr + 1]);     \
                mma16816(ACC[mt][nq], al[mt], bh[nt][pr], bh[nt][pr + 1]);     \
            }                                                                  \
    }                                                                          \
} while (0)

// ---------------------------------------------------------------------------
// Tensor-core (mma.sync) WaveNet layer. 2 CTAs/SM; cross-CTA latency hiding.
__global__ void __launch_bounds__(256, 2) tlayer_kernel(
    const float* __restrict__ res_in, float* __restrict__ res_out,
    float* __restrict__ out_acc,
    const __nv_bfloat16* __restrict__ wfg, const __nv_bfloat16* __restrict__ wsr,
    const float* __restrict__ fb, const float* __restrict__ gb,
    const float* __restrict__ sb, const float* __restrict__ rb,
    int d, int first)
{
    extern __shared__ char smem[];
    const uint32_t sbase = s2u(smem);
    float* sbias = (float*)smem;
    const uint32_t sA = sbase + OFF_A;
    const uint32_t sW = sbase + OFF_W;

    const int tid = threadIdx.x, wid = tid >> 5, lane = tid & 31;
    const int row0 = blockIdx.x * TM;
    const int batchStart = (row0 / T_LEN) * T_LEN;

    // prefetch phase-0 weights (f, chunk 0) while we stage A
    stage2(sW, wfg, wfg + (size_t)4 * 8192, tid);
    CP_COMMIT();

    for (int i = tid; i < 512; i += 256) {
        int grp = i >> 7, n = i & 127;
        const float* p = grp == 0 ? fb : grp == 1 ? gb : grp == 2 ? sb : rb;
        sbias[i] = p[n];
    }

    // ---- stage A = [prev(128) | cur(128)] as bf16 hi/lo, row-major [64][264]
    for (int idx = tid; idx < 2048; idx += 256) {
        int row = idx >> 5, ch = (idx & 31) * 8;
        int srow, c2;
        if (ch < 128) { srow = row0 + row - d; c2 = ch; }
        else          { srow = row0 + row;     c2 = ch - 128; }
        float v[8];
        if (srow >= batchStart) {
            const float4* sp = (const float4*)(res_in + (size_t)srow * RCH + c2);
            float4 a = sp[0], b2 = sp[1];
            v[0]=a.x; v[1]=a.y; v[2]=a.z; v[3]=a.w; v[4]=b2.x; v[5]=b2.y; v[6]=b2.z; v[7]=b2.w;
        } else {
            #pragma unroll
            for (int q = 0; q < 8; q++) v[q] = 0.f;
        }
        uint4 hp, lp;
        uint32_t* hw = (uint32_t*)&hp;
        uint32_t* lw = (uint32_t*)&lp;
        #pragma unroll
        for (int q = 0; q < 4; q++) {
            __nv_bfloat16 h0 = __float2bfloat16(v[2*q]),   h1 = __float2bfloat16(v[2*q+1]);
            __nv_bfloat16 l0 = __float2bfloat16(v[2*q]   - __bfloat162float(h0));
            __nv_bfloat16 l1 = __float2bfloat16(v[2*q+1] - __bfloat162float(h1));
            hw[q] = (uint32_t)__bfloat16_as_ushort(h0) | ((uint32_t)__bfloat16_as_ushort(h1) << 16);
            lw[q] = (uint32_t)__bfloat16_as_ushort(l0) | ((uint32_t)__bfloat16_as_ushort(l1) << 16);
        }
        uint32_t dst = sA + row * SA_STRIDE + ch * 2;
        STS128(dst, hp);
        STS128(dst + ALO_OFF, lp);
    }
    CP_WAIT_ALL();
    __syncthreads();

    // ldmatrix lane addressing
    const int mbase = (wid & 1) * 32;
    const int nbase = (wid >> 1) * 32;
    const int aRow = lane & 15, aCol = (lane >> 4) * 8;
    const int bm = lane >> 3;
    const int bRow = (lane & 7) + ((bm >> 1) * 8), bCol = (bm & 1) * 8;
    const uint32_t aBase = sA + (mbase + aRow) * SA_STRIDE + aCol * 2;
    const uint32_t bB = sW + (nbase + bRow) * W_STRIDE + bCol * 2;

    const int qrow = lane >> 2, qcol = (lane & 3) * 2;

    // ---- f/g: 8 phases (gate = p&1, chunk = p>>1); single W buffer
    {
        float accf[2][4][4], accg[2][4][4];
        #pragma unroll
        for (int mt = 0; mt < 2; mt++)
            #pragma unroll
            for (int nq = 0; nq < 4; nq++)
                #pragma unroll
                for (int q = 0; q < 4; q++) { accf[mt][nq][q] = 0.f; accg[mt][nq][q] = 0.f; }

        for (int p = 0; p < 8; p++) {
            int c = p >> 1;
            if (p & 1) COMPUTE_PHASE(accg, c);
            else       COMPUTE_PHASE(accf, c);
            __syncthreads();            // all warps done reading W
            if (p < 7) {
                int pn = p + 1, cn = pn >> 1, gate = pn & 1;
                stage2(sW, wfg + (size_t)(gate * 8 + cn) * 8192,
                           wfg + (size_t)(gate * 8 + 4 + cn) * 8192, tid);
            } else {
                stage2(sW, wsr, wsr + (size_t)2 * 8192, tid);   // sr phase 0
            }
            CP_COMMIT();
            CP_WAIT_ALL();
            __syncthreads();            // W ready (also: A reads done before epilogue)
        }

        // ---- gate epilogue: p = tanh(f+fb)*sigmoid(g+gb) -> hi/lo into A buffer
        #pragma unroll
        for (int mt = 0; mt < 2; mt++)
            #pragma unroll
            for (int nq = 0; nq < 4; nq++)
                #pragma unroll
                for (int rp = 0; rp < 2; rp++) {
                    int row = mbase + mt * 16 + qrow + rp * 8;
                    int col = nbase + nq * 8 + qcol;
                    float f0 = tanhf(accf[mt][nq][rp * 2]     + sbias[col]);
                    float f1 = tanhf(accf[mt][nq][rp * 2 + 1] + sbias[col + 1]);
                    float g0 = 1.f / (1.f + __expf(-(accg[mt][nq][rp * 2]     + sbias[128 + col])));
                    float g1 = 1.f / (1.f + __expf(-(accg[mt][nq][rp * 2 + 1] + sbias[128 + col + 1])));
                    float p0 = f0 * g0, p1 = f1 * g1;
                    __nv_bfloat16 h0 = __float2bfloat16(p0), h1 = __float2bfloat16(p1);
                    __nv_bfloat16 l0 = __float2bfloat16(p0 - __bfloat162float(h0));
                    __nv_bfloat16 l1 = __float2bfloat16(p1 - __bfloat162float(h1));
                    uint32_t hv = (uint32_t)__bfloat16_as_ushort(h0) | ((uint32_t)__bfloat16_as_ushort(h1) << 16);
                    uint32_t lv = (uint32_t)__bfloat16_as_ushort(l0) | ((uint32_t)__bfloat16_as_ushort(l1) << 16);
                    uint32_t dst = sA + row * SA_STRIDE + col * 2;
                    STS32(dst, hv);
                    STS32(dst + ALO_OFF, lv);
                }
    }
    __syncthreads();

    // ---- skip/res: 4 phases (skip c0, res c0, skip c1, res c1)
    float accs[2][4][4], accr[2][4][4];
    #pragma unroll
    for (int mt = 0; mt < 2; mt++)
        #pragma unroll
        for (int nq = 0; nq < 4; nq++)
            #pragma unroll
            for (int q = 0; q < 4; q++) { accs[mt][nq][q] = 0.f; accr[mt][nq][q] = 0.f; }

    for (int q = 0; q < 4; q++) {
        int c = q >> 1;
        if (q & 1) COMPUTE_PHASE(accr, c);
        else       COMPUTE_PHASE(accs, c);
        if (q < 3) {
            __syncthreads();
            int qn = q + 1, mat = qn & 1, cn = qn >> 1;
            stage2(sW, wsr + (size_t)(mat * 4 + cn) * 8192,
                       wsr + (size_t)(mat * 4 + 2 + cn) * 8192, tid);
            CP_COMMIT();
            CP_WAIT_ALL();
            __syncthreads();
        }
    }

    // ---- final epilogue
    #pragma unroll
    for (int mt = 0; mt < 2; mt++)
        #pragma unroll
        for (int nq = 0; nq < 4; nq++)
            #pragma unroll
            for (int rp = 0; rp < 2; rp++) {
                int row = mbase + mt * 16 + qrow + rp * 8;
                int col = nbase + nq * 8 + qcol;
                int grow = row0 + row;
                float s0 = accs[mt][nq][rp * 2]     + sbias[256 + col];
                float s1 = accs[mt][nq][rp * 2 + 1] + sbias[256 + col + 1];
                float* oa = out_acc + (size_t)grow * RCH + col;
                if (!first) {
                    float2 oo = *(const float2*)oa;
                    s0 += oo.x; s1 += oo.y;
                }
                *(float2*)oa = make_float2(s0, s1);
                float2 rv = *(const float2*)(res_in + (size_t)grow * RCH + col);
                float r0 = rv.x + accr[mt][nq][rp * 2]     + sbias[384 + col];
                float r1 = rv.y + accr[mt][nq][rp * 2 + 1] + sbias[384 + col + 1];
                *(float2*)(res_out + (size_t)grow * RCH + col) = make_float2(r0, r1);
            }
}

// ---------------------------------------------------------------------------
// Initial causal conv: K=32, 64 -> 128, dilation 1.  128 thr, 8x8 tile. (SIMT)
__global__ void __launch_bounds__(128, 2) init_kernel(
    const float* __restrict__ X, const float* __restrict__ W,
    const float* __restrict__ B, float* __restrict__ res_out)
{
    extern __shared__ float sm[];
    float* xt = sm;
    float* wb = sm + 96 * 64;
    const int tid  = threadIdx.x;
    const int row0 = blockIdx.x * TM;
    const int batchStart = (row0 / T_LEN) * T_LEN;

    for (int i = tid; i < 95 * 16; i += NT) {
        int r = i >> 4, c4 = i & 15;
        int src = row0 - 31 + r;
        float4 v = make_float4(0.f, 0.f, 0.f, 0.f);
        if (src >= batchStart) v = ((const float4*)(X + (size_t)src * 64))[c4];
        ((float4*)(xt + r * 64))[c4] = v;
    }

    const int ty = tid >> 4, tx = tid & 15;
    const int r0 = ty * 8, c0 = tx * 8;

    ull acc[8][4];
    #pragma unroll
    for (int j = 0; j < 4; j++) {
        ull b = pk2(B[c0 + 2*j], B[c0 + 2*j + 1]);
        #pragma unroll
        for (int rr = 0; rr < 8; rr++) acc[rr][j] = b;
    }

    for (int j = 0; j < 32; j++) {
        __syncthreads();
        const float4* ws = (const float4*)(W + (size_t)j * 64 * 128);
        for (int i = tid; i < 2048; i += NT) ((float4*)wb)[i] = ws[i];
        __syncthreads();
        #pragma unroll 2
        for (int kk = 0; kk < 64; kk += 2) {
            float2 ap[8];
            #pragma unroll
            for (int rr = 0; rr < 8; rr++)
                ap[rr] = *(const float2*)(xt + (r0 + rr + j) * 64 + kk);
            #pragma unroll
            for (int q = 0; q < 2; q++) {
                const float* wp = wb + (kk + q) * 128 + c0;
                ulonglong2 wa = *(const ulonglong2*)wp;
                ulonglong2 wc = *(const ulonglong2*)(wp + 4);
                #pragma unroll
                for (int rr = 0; rr < 8; rr++) {
                    float a = q ? ap[rr].y : ap[rr].x;
                    ull ad = pk2(a, a);
                    fma2(acc[rr][0], ad, wa.x);
                    fma2(acc[rr][1], ad, wa.y);
                    fma2(acc[rr][2], ad, wc.x);
                    fma2(acc[rr][3], ad, wc.y);
                }
            }
        }
    }
    #pragma unroll
    for (int rr = 0; rr < 8; rr++) {
        float o[8];
        #pragma unroll
        for (int j = 0; j < 4; j++) upk2(acc[rr][j], o[2*j], o[2*j+1]);
        float* dst = res_out + (size_t)(row0 + r0 + rr) * RCH + c0;
        ((float4*)dst)[0] = make_float4(o[0], o[1], o[2], o[3]);
        ((float4*)dst)[1] = make_float4(o[4], o[5], o[6], o[7]);
    }
}

// ---------------------------------------------------------------------------
// Post chain: one warp handles TWO rows, packed lo/hi into f32x2 lanes. (SIMT)
__global__ void __launch_bounds__(256) post_kernel(
    const float* __restrict__ out_acc,
    const float* __restrict__ s0w, const float* __restrict__ s0b,
    const float* __restrict__ srw, const float* __restrict__ srb,
    const float* __restrict__ fnw, const float* __restrict__ fnb,
    float* __restrict__ y)
{
    extern __shared__ float sm[];
    float* w0 = sm;
    float* wr = w0 + 4096;
    float* wf = wr + 31744;
    float* b0 = wf + 8192;
    float* br = b0 + 32;
    float* bf = br + 992;

    const int tid = threadIdx.x;
    for (int i = tid; i < 4096;  i += blockDim.x) w0[i] = s0w[i];
    for (int i = tid; i < 31744; i += blockDim.x) wr[i] = srw[i];
    for (int i = tid; i < 8192;  i += blockDim.x) wf[i] = fnw[i];
    for (int i = tid; i < 32;    i += blockDim.x) b0[i] = s0b[i];
    for (int i = tid; i < 992;   i += blockDim.x) br[i] = srb[i];
    for (int i = tid; i < 256;   i += blockDim.x) bf[i] = fnb[i];
    __syncthreads();

    const int warp = tid >> 5, lane = tid & 31;
    const int nwarp = blockDim.x >> 5;

    for (int pr = blockIdx.x * nwarp + warp; pr < BT / 2; pr += gridDim.x * nwarp) {
        const int rowA = pr * 2, rowB = pr * 2 + 1;
        float4 xa = ((const float4*)(out_acc + (size_t)rowA * RCH))[lane];
        float4 xb = ((const float4*)(out_acc + (size_t)rowB * RCH))[lane];
        xa.x = fmaxf(xa.x, 0.f); xa.y = fmaxf(xa.y, 0.f); xa.z = fmaxf(xa.z, 0.f); xa.w = fmaxf(xa.w, 0.f);
        xb.x = fmaxf(xb.x, 0.f); xb.y = fmaxf(xb.y, 0.f); xb.z = fmaxf(xb.z, 0.f); xb.w = fmaxf(xb.w, 0.f);
        ull xp0 = pk2(xa.x, xb.x), xp1 = pk2(xa.y, xb.y);
        ull xp2 = pk2(xa.z, xb.z), xp3 = pk2(xa.w, xb.w);

        float bb = b0[lane];
        ull h = pk2(bb, bb);
        #pragma unroll
        for (int s = 0; s < 32; s++) {
            ull v0 = __shfl_sync(0xffffffffu, xp0, s);
            ull v1 = __shfl_sync(0xffffffffu, xp1, s);
            ull v2 = __shfl_sync(0xffffffffu, xp2, s);
            ull v3 = __shfl_sync(0xffffffffu, xp3, s);
            float wv0 = w0[(s*4+0)*32 + lane];
            float wv1 = w0[(s*4+1)*32 + lane];
            float wv2 = w0[(s*4+2)*32 + lane];
            float wv3 = w0[(s*4+3)*32 + lane];
            fma2(h, v0, pk2(wv0, wv0));
            fma2(h, v1, pk2(wv1, wv1));
            fma2(h, v2, pk2(wv2, wv2));
            fma2(h, v3, pk2(wv3, wv3));
        }
        for (int li = 0; li < 31; li++) {
            float hl, hh; upk2(h, hl, hh);
            ull rv = pk2(fmaxf(hl, 0.f), fmaxf(hh, 0.f));
            const float* wp = wr + li * 1024;
            float bl = br[li*32 + lane];
            ull ha = pk2(bl, bl);
            ull hb = pk2(0.f, 0.f);
            #pragma unroll
            for (int s = 0; s < 32; s += 2) {
                ull ra  = __shfl_sync(0xffffffffu, rv, s);
                ull rb2 = __shfl_sync(0xffffffffu, rv, s + 1);
                float wA = wp[(s    )*32 + lane];
                float wB = wp[(s + 1)*32 + lane];
                fma2(ha, ra,  pk2(wA, wA));
                fma2(hb, rb2, pk2(wB, wB));
            }
            h = add2(ha, hb);
        }
        float hl, hh; upk2(h, hl, hh);
        ull rv = pk2(fmaxf(hl, 0.f), fmaxf(hh, 0.f));
        ull accP[8];
        #pragma unroll
        for (int u = 0; u < 8; u++) {
            float b = bf[lane*8 + u];
            accP[u] = pk2(b, b);
        }
        #pragma unroll
        for (int s = 0; s < 32; s++) {
            ull rs = __shfl_sync(0xffffffffu, rv, s);
            const float* wp = wf + s*256 + lane*8;
            float4 wq0 = *(const float4*)wp;
            float4 wq1 = *(const float4*)(wp + 4);
            fma2(accP[0], rs, pk2(wq0.x, wq0.x));
            fma2(accP[1], rs, pk2(wq0.y, wq0.y));
            fma2(accP[2], rs, pk2(wq0.z, wq0.z));
            fma2(accP[3], rs, pk2(wq0.w, wq0.w));
            fma2(accP[4], rs, pk2(wq1.x, wq1.x));
            fma2(accP[5], rs, pk2(wq1.y, wq1.y));
            fma2(accP[6], rs, pk2(wq1.z, wq1.z));
            fma2(accP[7], rs, pk2(wq1.w, wq1.w));
        }
        float oa[8], ob[8];
        #pragma unroll
        for (int u = 0; u < 8; u++) upk2(accP[u], oa[u], ob[u]);
        float4* ya = (float4*)(y + (size_t)rowA * 256 + lane * 8);
        ya[0] = make_float4(oa[0], oa[1], oa[2], oa[3]);
        ya[1] = make_float4(oa[4], oa[5], oa[6], oa[7]);
        float4* yb = (float4*)(y + (size_t)rowB * 256 + lane * 8);
        yb[0] = make_float4(ob[0], ob[1], ob[2], ob[3]);
        yb[1] = make_float4(ob[4], ob[5], ob[6], ob[7]);
    }
}

// ---------------------------------------------------------------------------
extern "C" void kernel_launch(void* const* d_in, const int* in_sizes, int n_in,
                              void* d_out, int out_size)
{
    const float* X       = (const float*)d_in[0];
    const float* init_w  = (const float*)d_in[1];
    const float* init_b  = (const float*)d_in[2];
    const float* f_w     = (const float*)d_in[3];
    const float* f_b     = (const float*)d_in[4];
    const float* g_w     = (const float*)d_in[5];
    const float* g_b     = (const float*)d_in[6];
    const float* skip_w  = (const float*)d_in[7];
    const float* skip_b  = (const float*)d_in[8];
    const float* res_w   = (const float*)d_in[9];
    const float* res_b   = (const float*)d_in[10];
    const float* skip0_w = (const float*)d_in[11];
    const float* skip0_b = (const float*)d_in[12];
    const float* skipr_w = (const float*)d_in[13];
    const float* skipr_b = (const float*)d_in[14];
    const float* final_w = (const float*)d_in[15];
    const float* final_b = (const float*)d_in[16];
    float* y = (float*)d_out;

    float *resA, *resB, *outacc;
    __nv_bfloat16 *wfg, *wsr;
    cudaGetSymbolAddress((void**)&resA,   g_resA);
    cudaGetSymbolAddress((void**)&resB,   g_resB);
    cudaGetSymbolAddress((void**)&outacc, g_outacc);
    cudaGetSymbolAddress((void**)&wfg,    g_wfg);
    cudaGetSymbolAddress((void**)&wsr,    g_wsr);

    const int INIT_SMEM  = (96*64 + 64*128) * 4;
    const int POST_SMEM  = (4096 + 31744 + 8192 + 32 + 992 + 256) * 4;
    cudaFuncSetAttribute(init_kernel,   cudaFuncAttributeMaxDynamicSharedMemorySize, INIT_SMEM);
    cudaFuncSetAttribute(tlayer_kernel, cudaFuncAttributeMaxDynamicSharedMemorySize, LSMEM);
    cudaFuncSetAttribute(post_kernel,   cudaFuncAttributeMaxDynamicSharedMemorySize, POST_SMEM);

    prep_kernel<<<2048, 256>>>(f_w, g_w, skip_w, res_w);
    init_kernel<<<BT / TM, NT, INIT_SMEM>>>(X, init_w, init_b, resA);

    static const int DIL[20] = {1,2,4,8,16,32,64,128,256,512,
                                1,2,4,8,16,32,64,128,256,512};
    for (int i = 0; i < 20; i++) {
        const float* rin  = (i & 1) ? resB : resA;
        float*       rout = (i & 1) ? resA : resB;
        tlayer_kernel<<<BT / TM, 256, LSMEM>>>(
            rin, rout, outacc,
            wfg + (size_t)i * 16 * 8192, wsr + (size_t)i * 8 * 8192,
            f_b + i * RCH, g_b + i * RCH, skip_b + i * RCH, res_b + i * RCH,
            DIL[i], (i == 0) ? 1 : 0);
    }

    post_kernel<<<1184, 256, POST_SMEM>>>(outacc, skip0_w, skip0_b,
                                          skipr_w, skipr_b, final_w, final_b, y);
}

// round 12
// speedup vs baseline: 2.5165x; 1.0007x over previous
#include <cuda_runtime.h>
#include <cuda_bf16.h>
#include <math.h>
#include <stdint.h>

typedef unsigned long long ull;

#define BT    65536
#define T_LEN 16384
#define RCH   128
#define TM    64
#define NT    128

// ---------------- scratch ---------------------------------------------------
__device__ float g_resA[BT * RCH];
__device__ float g_resB[BT * RCH];
__device__ float g_outacc[BT * RCH];
// prepped weights: bf16 hi/lo K-major tiles [128 n x 64 k] (8192 elems each)
// fg per layer: tile idx = gate*8 + part*4 + chunk(4)
// sr per layer: tile idx = mat*4 + part*2 + chunk(2)
__device__ __nv_bfloat16 g_wfg[20 * 16 * 8192];
__device__ __nv_bfloat16 g_wsr[20 * 8 * 8192];

// ---------------- packed f32x2 helpers (SIMT kernels) -----------------------
__device__ __forceinline__ ull pk2(float lo, float hi) {
    ull r; asm("mov.b64 %0, {%1, %2};" : "=l"(r) : "f"(lo), "f"(hi)); return r;
}
__device__ __forceinline__ void upk2(ull v, float& lo, float& hi) {
    asm("mov.b64 {%0, %1}, %2;" : "=f"(lo), "=f"(hi) : "l"(v));
}
__device__ __forceinline__ void fma2(ull& d, ull a, ull b) {
    asm("fma.rn.f32x2 %0, %1, %2, %0;" : "+l"(d) : "l"(a), "l"(b));
}
__device__ __forceinline__ ull add2(ull a, ull b) {
    ull r; asm("add.rn.f32x2 %0, %1, %2;" : "=l"(r) : "l"(a), "l"(b)); return r;
}

// ---------------- warp-mma helpers ------------------------------------------
__device__ __forceinline__ uint32_t s2u(const void* p) {
    uint32_t a;
    asm("{ .reg .u64 t; cvta.to.shared.u64 t, %1; cvt.u32.u64 %0, t; }" : "=r"(a) : "l"(p));
    return a;
}
__device__ __forceinline__ void ldm4(uint32_t* r, uint32_t addr) {
    asm volatile("ldmatrix.sync.aligned.m8n8.x4.shared.b16 {%0,%1,%2,%3}, [%4];"
                 : "=r"(r[0]), "=r"(r[1]), "=r"(r[2]), "=r"(r[3]) : "r"(addr));
}
__device__ __forceinline__ void mma16816(float* d, const uint32_t* a, uint32_t b0, uint32_t b1) {
    asm volatile("mma.sync.aligned.m16n8k16.row.col.f32.bf16.bf16.f32 "
                 "{%0,%1,%2,%3}, {%4,%5,%6,%7}, {%8,%9}, {%0,%1,%2,%3};"
                 : "+f"(d[0]), "+f"(d[1]), "+f"(d[2]), "+f"(d[3])
                 : "r"(a[0]), "r"(a[1]), "r"(a[2]), "r"(a[3]), "r"(b0), "r"(b1));
}
#define STS128(a, v) \
    asm volatile("st.shared.v4.b32 [%0], {%1,%2,%3,%4};" :: "r"(a), "r"((v).x), "r"((v).y), "r"((v).z), "r"((v).w))
#define STS32(a, v) asm volatile("st.shared.b32 [%0], %1;" :: "r"(a), "r"(v))
#define CP_ASYNC16(d, s) asm volatile("cp.async.cg.shared.global [%0], [%1], 16;" :: "r"(d), "l"(s))
#define CP_COMMIT()      asm volatile("cp.async.commit_group;" ::: "memory")
#define CP_WAIT_ALL()    asm volatile("cp.async.wait_all;" ::: "memory")

// smem layout (bytes): bias[512 f32] | A hi [64x264 bf16] | A lo | W: 1 buffer x 2 tiles
#define SA_STRIDE 528
#define ALO_OFF   33792
#define W_STRIDE  144
#define W_TILE    18432
#define OFF_A     2048
#define OFF_W     (OFF_A + 2 * 33792)     // 69632
#define LSMEM     (OFF_W + 2 * W_TILE)    // 106496  -> 2 CTAs/SM

// ---------------------------------------------------------------------------
// Weight prep: split fp32 weights to bf16 hi/lo, transpose to [n][k] tiles.
__global__ void prep_kernel(const float* __restrict__ fw, const float* __restrict__ gw,
                            const float* __restrict__ sw, const float* __restrict__ rw)
{
    const int total_fg = 20 * 2 * 4 * 128 * 64;
    const int total_sr = 20 * 2 * 2 * 128 * 64;
    for (int idx = blockIdx.x * blockDim.x + threadIdx.x; idx < total_fg + total_sr;
         idx += gridDim.x * blockDim.x) {
        if (idx < total_fg) {
            int k = idx & 63, n = (idx >> 6) & 127, c = (idx >> 13) & 3;
            int gate = (idx >> 15) & 1, layer = idx >> 16;
            int kk = c * 64 + k, tap = kk >> 7, kc = kk & 127;
            const float* src = gate ? gw : fw;
            float w = src[(((size_t)layer * 2 + tap) * 128 + kc) * 128 + n];
            __nv_bfloat16 hi = __float2bfloat16(w);
            __nv_bfloat16 lo = __float2bfloat16(w - __bfloat162float(hi));
            size_t tbase = ((size_t)layer * 16 + gate * 8) * 8192 + (size_t)n * 64 + k;
            g_wfg[tbase + (size_t)(0 * 4 + c) * 8192] = hi;
            g_wfg[tbase + (size_t)(1 * 4 + c) * 8192] = lo;
        } else {
            int j = idx - total_fg;
            int k = j & 63, n = (j >> 6) & 127, c = (j >> 13) & 1;
            int mat = (j >> 14) & 1, layer = j >> 15;
            int kc = c * 64 + k;
            const float* src = mat ? rw : sw;
            float w = src[((size_t)layer * 128 + kc) * 128 + n];
            __nv_bfloat16 hi = __float2bfloat16(w);
            __nv_bfloat16 lo = __float2bfloat16(w - __bfloat162float(hi));
            size_t tbase = ((size_t)layer * 8 + mat * 4) * 8192 + (size_t)n * 64 + k;
            g_wsr[tbase + (size_t)(0 * 2 + c) * 8192] = hi;
            g_wsr[tbase + (size_t)(1 * 2 + c) * 8192] = lo;
        }
    }
}

// stage one phase's weights (hi tile + lo tile) into the W buffer via cp.async
__device__ __forceinline__ void stage2(uint32_t dst, const __nv_bfloat16* __restrict__ hi,
                                       const __nv_bfloat16* __restrict__ lo, int tid)
{
    #pragma unroll
    for (int r = 0; r < 8; r++) {
        int i = r * 256 + tid;
        int t = i >> 10, u = i & 1023, n = u >> 3, ku = u & 7;
        const __nv_bfloat16* s = (t ? lo : hi) + (size_t)n * 64 + ku * 8;
        CP_ASYNC16(dst + t * W_TILE + n * W_STRIDE + ku * 16, s);
    }
}

// one phase of MMAs: acc += A(hi,lo) x W(hi,lo) over k-chunk cc
#define COMPUTE_PHASE(ACC, cc) do {                                            \
    _Pragma("unroll")                                                          \
    for (int ks = 0; ks < 4; ks++) {                                           \
        const int kA2 = ((cc) * 64 + ks * 16) * 2, kW2 = ks * 32;              \
        uint32_t ah[2][4], al[2][4], bh[2][4], bl[2][4];                       \
        ldm4(ah[0], aBase + kA2);                                              \
        ldm4(ah[1], aBase + 16 * SA_STRIDE + kA2);                             \
        ldm4(al[0], aBase + ALO_OFF + kA2);                                    \
        ldm4(al[1], aBase + ALO_OFF + 16 * SA_STRIDE + kA2);                   \
        ldm4(bh[0], bB + kW2);                                                 \
        ldm4(bh[1], bB + 16 * W_STRIDE + kW2);                                 \
        ldm4(bl[0], bB + W_TILE + kW2);                                        \
        ldm4(bl[1], bB + W_TILE + 16 * W_STRIDE + kW2);                        \
        _Pragma("unroll")                                                      \
        for (int mt = 0; mt < 2; mt++)                                         \
            _Pragma("unroll")                                                  \
            for (int nq = 0; nq < 4; nq++) {                                   \
                int nt = nq >> 1, pr = (nq & 1) * 2;                           \
                mma16816(ACC[mt][nq], ah[mt], bh[nt][pr], bh[nt][pr + 1]);     \
                mma16816(ACC[mt][nq], ah[mt], bl[nt][pr], bl[nt][pr + 1]);     \
                mma16816(ACC[mt][nq], al[mt], bh[nt][pr], bh[nt][pr + 1]);     \
            }                                                                  \
    }                                                                          \
} while (0)

// ---------------------------------------------------------------------------
// Tensor-core (mma.sync) WaveNet layer. 2 CTAs/SM; cross-CTA latency hiding.
__global__ void __launch_bounds__(256, 2) tlayer_kernel(
    const float* __restrict__ res_in, float* __restrict__ res_out,
    float* __restrict__ out_acc,
    const __nv_bfloat16* __restrict__ wfg, const __nv_bfloat16* __restrict__ wsr,
    const float* __restrict__ fb, const float* __restrict__ gb,
    const float* __restrict__ sb, const float* __restrict__ rb,
    int d, int first)
{
    extern __shared__ char smem[];
    const uint32_t sbase = s2u(smem);
    float* sbias = (float*)smem;
    const uint32_t sA = sbase + OFF_A;
    const uint32_t sW = sbase + OFF_W;

    const int tid = threadIdx.x, wid = tid >> 5, lane = tid & 31;
    const int row0 = blockIdx.x * TM;
    const int batchStart = (row0 / T_LEN) * T_LEN;

    // prefetch phase-0 weights (f, chunk 0) while we stage A
    stage2(sW, wfg, wfg + (size_t)4 * 8192, tid);
    CP_COMMIT();

    for (int i = tid; i < 512; i += 256) {
        int grp = i >> 7, n = i & 127;
        const float* p = grp == 0 ? fb : grp == 1 ? gb : grp == 2 ? sb : rb;
        sbias[i] = p[n];
    }

    // ---- stage A = [prev(128) | cur(128)] as bf16 hi/lo, row-major [64][264]
    for (int idx = tid; idx < 2048; idx += 256) {
        int row = idx >> 5, ch = (idx & 31) * 8;
        int srow, c2;
        if (ch < 128) { srow = row0 + row - d; c2 = ch; }
        else          { srow = row0 + row;     c2 = ch - 128; }
        float v[8];
        if (srow >= batchStart) {
            const float4* sp = (const float4*)(res_in + (size_t)srow * RCH + c2);
            float4 a = sp[0], b2 = sp[1];
            v[0]=a.x; v[1]=a.y; v[2]=a.z; v[3]=a.w; v[4]=b2.x; v[5]=b2.y; v[6]=b2.z; v[7]=b2.w;
        } else {
            #pragma unroll
            for (int q = 0; q < 8; q++) v[q] = 0.f;
        }
        uint4 hp, lp;
        uint32_t* hw = (uint32_t*)&hp;
        uint32_t* lw = (uint32_t*)&lp;
        #pragma unroll
        for (int q = 0; q < 4; q++) {
            __nv_bfloat16 h0 = __float2bfloat16(v[2*q]),   h1 = __float2bfloat16(v[2*q+1]);
            __nv_bfloat16 l0 = __float2bfloat16(v[2*q]   - __bfloat162float(h0));
            __nv_bfloat16 l1 = __float2bfloat16(v[2*q+1] - __bfloat162float(h1));
            hw[q] = (uint32_t)__bfloat16_as_ushort(h0) | ((uint32_t)__bfloat16_as_ushort(h1) << 16);
            lw[q] = (uint32_t)__bfloat16_as_ushort(l0) | ((uint32_t)__bfloat16_as_ushort(l1) << 16);
        }
        uint32_t dst = sA + row * SA_STRIDE + ch * 2;
        STS128(dst, hp);
        STS128(dst + ALO_OFF, lp);
    }
    CP_WAIT_ALL();
    __syncthreads();

    // ldmatrix lane addressing
    const int mbase = (wid & 1) * 32;
    const int nbase = (wid >> 1) * 32;
    const int aRow = lane & 15, aCol = (lane >> 4) * 8;
    const int bm = lane >> 3;
    const int bRow = (lane & 7) + ((bm >> 1) * 8), bCol = (bm & 1) * 8;
    const uint32_t aBase = sA + (mbase + aRow) * SA_STRIDE + aCol * 2;
    const uint32_t bB = sW + (nbase + bRow) * W_STRIDE + bCol * 2;

    const int qrow = lane >> 2, qcol = (lane & 3) * 2;

    // ---- f/g: 8 phases (gate = p&1, chunk = p>>1); single W buffer
    {
        float accf[2][4][4], accg[2][4][4];
        #pragma unroll
        for (int mt = 0; mt < 2; mt++)
            #pragma unroll
            for (int nq = 0; nq < 4; nq++)
                #pragma unroll
                for (int q = 0; q < 4; q++) { accf[mt][nq][q] = 0.f; accg[mt][nq][q] = 0.f; }

        for (int p = 0; p < 8; p++) {
            int c = p >> 1;
            if (p & 1) COMPUTE_PHASE(accg, c);
            else       COMPUTE_PHASE(accf, c);
            __syncthreads();            // all warps done reading W
            if (p < 7) {
                int pn = p + 1, cn = pn >> 1, gate = pn & 1;
                stage2(sW, wfg + (size_t)(gate * 8 + cn) * 8192,
                           wfg + (size_t)(gate * 8 + 4 + cn) * 8192, tid);
            } else {
                stage2(sW, wsr, wsr + (size_t)2 * 8192, tid);   // sr phase 0
            }
            CP_COMMIT();
            CP_WAIT_ALL();
            __syncthreads();            // W ready (also: A reads done before epilogue)
        }

        // ---- gate epilogue: p = tanh(f+fb)*sigmoid(g+gb) -> hi/lo into A buffer
        #pragma unroll
        for (int mt = 0; mt < 2; mt++)
            #pragma unroll
            for (int nq = 0; nq < 4; nq++)
                #pragma unroll
                for (int rp = 0; rp < 2; rp++) {
                    int row = mbase + mt * 16 + qrow + rp * 8;
                    int col = nbase + nq * 8 + qcol;
                    float f0 = tanhf(accf[mt][nq][rp * 2]     + sbias[col]);
                    float f1 = tanhf(accf[mt][nq][rp * 2 + 1] + sbias[col + 1]);
                    float g0 = 1.f / (1.f + __expf(-(accg[mt][nq][rp * 2]     + sbias[128 + col])));
                    float g1 = 1.f / (1.f + __expf(-(accg[mt][nq][rp * 2 + 1] + sbias[128 + col + 1])));
                    float p0 = f0 * g0, p1 = f1 * g1;
                    __nv_bfloat16 h0 = __float2bfloat16(p0), h1 = __float2bfloat16(p1);
                    __nv_bfloat16 l0 = __float2bfloat16(p0 - __bfloat162float(h0));
                    __nv_bfloat16 l1 = __float2bfloat16(p1 - __bfloat162float(h1));
                    uint32_t hv = (uint32_t)__bfloat16_as_ushort(h0) | ((uint32_t)__bfloat16_as_ushort(h1) << 16);
                    uint32_t lv = (uint32_t)__bfloat16_as_ushort(l0) | ((uint32_t)__bfloat16_as_ushort(l1) << 16);
                    uint32_t dst = sA + row * SA_STRIDE + col * 2;
                    STS32(dst, hv);
                    STS32(dst + ALO_OFF, lv);
                }
    }
    __syncthreads();

    // ---- skip/res: 4 phases (skip c0, res c0, skip c1, res c1)
    float accs[2][4][4], accr[2][4][4];
    #pragma unroll
    for (int mt = 0; mt < 2; mt++)
        #pragma unroll
        for (int nq = 0; nq < 4; nq++)
            #pragma unroll
            for (int q = 0; q < 4; q++) { accs[mt][nq][q] = 0.f; accr[mt][nq][q] = 0.f; }

    for (int q = 0; q < 4; q++) {
        int c = q >> 1;
        if (q & 1) COMPUTE_PHASE(accr, c);
        else       COMPUTE_PHASE(accs, c);
        if (q < 3) {
            __syncthreads();
            int qn = q + 1, mat = qn & 1, cn = qn >> 1;
            stage2(sW, wsr + (size_t)(mat * 4 + cn) * 8192,
                       wsr + (size_t)(mat * 4 + 2 + cn) * 8192, tid);
            CP_COMMIT();
            CP_WAIT_ALL();
            __syncthreads();
        }
    }

    // ---- final epilogue
    #pragma unroll
    for (int mt = 0; mt < 2; mt++)
        #pragma unroll
        for (int nq = 0; nq < 4; nq++)
            #pragma unroll
            for (int rp = 0; rp < 2; rp++) {
                int row = mbase + mt * 16 + qrow + rp * 8;
                int col = nbase + nq * 8 + qcol;
                int grow = row0 + row;
                float s0 = accs[mt][nq][rp * 2]     + sbias[256 + col];
                float s1 = accs[mt][nq][rp * 2 + 1] + sbias[256 + col + 1];
                float* oa = out_acc + (size_t)grow * RCH + col;
                if (!first) {
                    float2 oo = *(const float2*)oa;
                    s0 += oo.x; s1 += oo.y;
                }
                *(float2*)oa = make_float2(s0, s1);
                float2 rv = *(const float2*)(res_in + (size_t)grow * RCH + col);
                float r0 = rv.x + accr[mt][nq][rp * 2]     + sbias[384 + col];
                float r1 = rv.y + accr[mt][nq][rp * 2 + 1] + sbias[384 + col + 1];
                *(float2*)(res_out + (size_t)grow * RCH + col) = make_float2(r0, r1);
            }
}

// ---------------------------------------------------------------------------
// Initial causal conv: K=32, 64 -> 128, dilation 1.  128 thr, 8x8 tile. (SIMT)
__global__ void __launch_bounds__(128, 2) init_kernel(
    const float* __restrict__ X, const float* __restrict__ W,
    const float* __restrict__ B, float* __restrict__ res_out)
{
    extern __shared__ float sm[];
    float* xt = sm;
    float* wb = sm + 96 * 64;
    const int tid  = threadIdx.x;
    const int row0 = blockIdx.x * TM;
    const int batchStart = (row0 / T_LEN) * T_LEN;

    for (int i = tid; i < 95 * 16; i += NT) {
        int r = i >> 4, c4 = i & 15;
        int src = row0 - 31 + r;
        float4 v = make_float4(0.f, 0.f, 0.f, 0.f);
        if (src >= batchStart) v = ((const float4*)(X + (size_t)src * 64))[c4];
        ((float4*)(xt + r * 64))[c4] = v;
    }

    const int ty = tid >> 4, tx = tid & 15;
    const int r0 = ty * 8, c0 = tx * 8;

    ull acc[8][4];
    #pragma unroll
    for (int j = 0; j < 4; j++) {
        ull b = pk2(B[c0 + 2*j], B[c0 + 2*j + 1]);
        #pragma unroll
        for (int rr = 0; rr < 8; rr++) acc[rr][j] = b;
    }

    for (int j = 0; j < 32; j++) {
        __syncthreads();
        const float4* ws = (const float4*)(W + (size_t)j * 64 * 128);
        for (int i = tid; i < 2048; i += NT) ((float4*)wb)[i] = ws[i];
        __syncthreads();
        #pragma unroll 2
        for (int kk = 0; kk < 64; kk += 2) {
            float2 ap[8];
            #pragma unroll
            for (int rr = 0; rr < 8; rr++)
                ap[rr] = *(const float2*)(xt + (r0 + rr + j) * 64 + kk);
            #pragma unroll
            for (int q = 0; q < 2; q++) {
                const float* wp = wb + (kk + q) * 128 + c0;
                ulonglong2 wa = *(const ulonglong2*)wp;
                ulonglong2 wc = *(const ulonglong2*)(wp + 4);
                #pragma unroll
                for (int rr = 0; rr < 8; rr++) {
                    float a = q ? ap[rr].y : ap[rr].x;
                    ull ad = pk2(a, a);
                    fma2(acc[rr][0], ad, wa.x);
                    fma2(acc[rr][1], ad, wa.y);
                    fma2(acc[rr][2], ad, wc.x);
                    fma2(acc[rr][3], ad, wc.y);
                }
            }
        }
    }
    #pragma unroll
    for (int rr = 0; rr < 8; rr++) {
        float o[8];
        #pragma unroll
        for (int j = 0; j < 4; j++) upk2(acc[rr][j], o[2*j], o[2*j+1]);
        float* dst = res_out + (size_t)(row0 + r0 + rr) * RCH + c0;
        ((float4*)dst)[0] = make_float4(o[0], o[1], o[2], o[3]);
        ((float4*)dst)[1] = make_float4(o[4], o[5], o[6], o[7]);
    }
}

// ---------------------------------------------------------------------------
// Post chain: one warp handles TWO rows, packed lo/hi into f32x2 lanes. (SIMT)
__global__ void __launch_bounds__(256) post_kernel(
    const float* __restrict__ out_acc,
    const float* __restrict__ s0w, const float* __restrict__ s0b,
    const float* __restrict__ srw, const float* __restrict__ srb,
    const float* __restrict__ fnw, const float* __restrict__ fnb,
    float* __restrict__ y)
{
    extern __shared__ float sm[];
    float* w0 = sm;
    float* wr = w0 + 4096;
    float* wf = wr + 31744;
    float* b0 = wf + 8192;
    float* br = b0 + 32;
    float* bf = br + 992;

    const int tid = threadIdx.x;
    for (int i = tid; i < 4096;  i += blockDim.x) w0[i] = s0w[i];
    for (int i = tid; i < 31744; i += blockDim.x) wr[i] = srw[i];
    for (int i = tid; i < 8192;  i += blockDim.x) wf[i] = fnw[i];
    for (int i = tid; i < 32;    i += blockDim.x) b0[i] = s0b[i];
    for (int i = tid; i < 992;   i += blockDim.x) br[i] = srb[i];
    for (int i = tid; i < 256;   i += blockDim.x) bf[i] = fnb[i];
    __syncthreads();

    const int warp = tid >> 5, lane = tid & 31;
    const int nwarp = blockDim.x >> 5;

    for (int pr = blockIdx.x * nwarp + warp; pr < BT / 2; pr += gridDim.x * nwarp) {
        const int rowA = pr * 2, rowB = pr * 2 + 1;
        float4 xa = ((const float4*)(out_acc + (size_t)rowA * RCH))[lane];
        float4 xb = ((const float4*)(out_acc + (size_t)rowB * RCH))[lane];
        xa.x = fmaxf(xa.x, 0.f); xa.y = fmaxf(xa.y, 0.f); xa.z = fmaxf(xa.z, 0.f); xa.w = fmaxf(xa.w, 0.f);
        xb.x = fmaxf(xb.x, 0.f); xb.y = fmaxf(xb.y, 0.f); xb.z = fmaxf(xb.z, 0.f); xb.w = fmaxf(xb.w, 0.f);
        ull xp0 = pk2(xa.x, xb.x), xp1 = pk2(xa.y, xb.y);
        ull xp2 = pk2(xa.z, xb.z), xp3 = pk2(xa.w, xb.w);

        float bb = b0[lane];
        ull h = pk2(bb, bb);
        #pragma unroll
        for (int s = 0; s < 32; s++) {
            ull v0 = __shfl_sync(0xffffffffu, xp0, s);
            ull v1 = __shfl_sync(0xffffffffu, xp1, s);
            ull v2 = __shfl_sync(0xffffffffu, xp2, s);
            ull v3 = __shfl_sync(0xffffffffu, xp3, s);
            float wv0 = w0[(s*4+0)*32 + lane];
            float wv1 = w0[(s*4+1)*32 + lane];
            float wv2 = w0[(s*4+2)*32 + lane];
            float wv3 = w0[(s*4+3)*32 + lane];
            fma2(h, v0, pk2(wv0, wv0));
            fma2(h, v1, pk2(wv1, wv1));
            fma2(h, v2, pk2(wv2, wv2));
            fma2(h, v3, pk2(wv3, wv3));
        }
        for (int li = 0; li < 31; li++) {
            float hl, hh; upk2(h, hl, hh);
            ull rv = pk2(fmaxf(hl, 0.f), fmaxf(hh, 0.f));
            const float* wp = wr + li * 1024;
            float bl = br[li*32 + lane];
            ull ha = pk2(bl, bl);
            ull hb = pk2(0.f, 0.f);
            #pragma unroll
            for (int s = 0; s < 32; s += 2) {
                ull ra  = __shfl_sync(0xffffffffu, rv, s);
                ull rb2 = __shfl_sync(0xffffffffu, rv, s + 1);
                float wA = wp[(s    )*32 + lane];
                float wB = wp[(s + 1)*32 + lane];
                fma2(ha, ra,  pk2(wA, wA));
                fma2(hb, rb2, pk2(wB, wB));
            }
            h = add2(ha, hb);
        }
        float hl, hh; upk2(h, hl, hh);
        ull rv = pk2(fmaxf(hl, 0.f), fmaxf(hh, 0.f));
        ull accP[8];
        #pragma unroll
        for (int u = 0; u < 8; u++) {
            float b = bf[lane*8 + u];
            accP[u] = pk2(b, b);
        }
        #pragma unroll
        for (int s = 0; s < 32; s++) {
            ull rs = __shfl_sync(0xffffffffu, rv, s);
            const float* wp = wf + s*256 + lane*8;
            float4 wq0 = *(const float4*)wp;
            float4 wq1 = *(const float4*)(wp + 4);
            fma2(accP[0], rs, pk2(wq0.x, wq0.x));
            fma2(accP[1], rs, pk2(wq0.y, wq0.y));
            fma2(accP[2], rs, pk2(wq0.z, wq0.z));
            fma2(accP[3], rs, pk2(wq0.w, wq0.w));
            fma2(accP[4], rs, pk2(wq1.x, wq1.x));
            fma2(accP[5], rs, pk2(wq1.y, wq1.y));
            fma2(accP[6], rs, pk2(wq1.z, wq1.z));
            fma2(accP[7], rs, pk2(wq1.w, wq1.w));
        }
        float oa[8], ob[8];
        #pragma unroll
        for (int u = 0; u < 8; u++) upk2(accP[u], oa[u], ob[u]);
        float4* ya = (float4*)(y + (size_t)rowA * 256 + lane * 8);
        ya[0] = make_float4(oa[0], oa[1], oa[2], oa[3]);
        ya[1] = make_float4(oa[4], oa[5], oa[6], oa[7]);
        float4* yb = (float4*)(y + (size_t)rowB * 256 + lane * 8);
        yb[0] = make_float4(ob[0], ob[1], ob[2], ob[3]);
        yb[1] = make_float4(ob[4], ob[5], ob[6], ob[7]);
    }
}

// ---------------------------------------------------------------------------
extern "C" void kernel_launch(void* const* d_in, const int* in_sizes, int n_in,
                              void* d_out, int out_size)
{
    const float* X       = (const float*)d_in[0];
    const float* init_w  = (const float*)d_in[1];
    const float* init_b  = (const float*)d_in[2];
    const float* f_w     = (const float*)d_in[3];
    const float* f_b     = (const float*)d_in[4];
    const float* g_w     = (const float*)d_in[5];
    const float* g_b     = (const float*)d_in[6];
    const float* skip_w  = (const float*)d_in[7];
    const float* skip_b  = (const float*)d_in[8];
    const float* res_w   = (const float*)d_in[9];
    const float* res_b   = (const float*)d_in[10];
    const float* skip0_w = (const float*)d_in[11];
    const float* skip0_b = (const float*)d_in[12];
    const float* skipr_w = (const float*)d_in[13];
    const float* skipr_b = (const float*)d_in[14];
    const float* final_w = (const float*)d_in[15];
    const float* final_b = (const float*)d_in[16];
    float* y = (float*)d_out;

    float *resA, *resB, *outacc;
    __nv_bfloat16 *wfg, *wsr;
    cudaGetSymbolAddress((void**)&resA,   g_resA);
    cudaGetSymbolAddress((void**)&resB,   g_resB);
    cudaGetSymbolAddress((void**)&outacc, g_outacc);
    cudaGetSymbolAddress((void**)&wfg,    g_wfg);
    cudaGetSymbolAddress((void**)&wsr,    g_wsr);

    const int INIT_SMEM  = (96*64 + 64*128) * 4;
    const int POST_SMEM  = (4096 + 31744 + 8192 + 32 + 992 + 256) * 4;
    cudaFuncSetAttribute(init_kernel,   cudaFuncAttributeMaxDynamicSharedMemorySize, INIT_SMEM);
    cudaFuncSetAttribute(tlayer_kernel, cudaFuncAttributeMaxDynamicSharedMemorySize, LSMEM);
    cudaFuncSetAttribute(post_kernel,   cudaFuncAttributeMaxDynamicSharedMemorySize, POST_SMEM);

    prep_kernel<<<2048, 256>>>(f_w, g_w, skip_w, res_w);
    init_kernel<<<BT / TM, NT, INIT_SMEM>>>(X, init_w, init_b, resA);

    static const int DIL[20] = {1,2,4,8,16,32,64,128,256,512,
                                1,2,4,8,16,32,64,128,256,512};
    for (int i = 0; i < 20; i++) {
        const float* rin  = (i & 1) ? resB : resA;
        float*       rout = (i & 1) ? resA : resB;
        tlayer_kernel<<<BT / TM, 256, LSMEM>>>(
            rin, rout, outacc,
            wfg + (size_t)i * 16 * 8192, wsr + (size_t)i * 8 * 8192,
            f_b + i * RCH, g_b + i * RCH, skip_b + i * RCH, res_b + i * RCH,
            DIL[i], (i == 0) ? 1 : 0);
    }

    post_kernel<<<1184, 256, POST_SMEM>>>(outacc, skip0_w, skip0_b,
                                          skipr_w, skipr_b, final_w, final_b, y);
}